// round 1
// baseline (speedup 1.0000x reference)
#include <cuda_runtime.h>
#include <math.h>

// ---------------------------------------------------------------------------
// Problem constants (from reference): N0=10000, D=256, O=128, DW=128
// ---------------------------------------------------------------------------
#define N0_DOCS 10000
#define MAXN1 50000
#define MAXN2 30000

// Scratch (device globals; no allocation allowed)
__device__ float g_l1_1[MAXN1 * 128];
__device__ float g_h1  [MAXN1 * 128];
__device__ float g_l2_1[MAXN1 * 128];
__device__ float g_l1_2[MAXN2 * 128];
__device__ float g_h2  [MAXN2 * 128];
__device__ float g_l2_2[MAXN2 * 128];
__device__ float g_r0 [N0_DOCS * 128];
__device__ float g_r0s[N0_DOCS * 128];
__device__ float g_rA [N0_DOCS * 128];
__device__ float g_rB [N0_DOCS * 128];
__device__ float g_rw [N0_DOCS * 128];

// ---------------------------------------------------------------------------
// GEMM + bias + ReLU:  C[M,128] = relu(A[M,K] @ W[K,128] + b)
// Tile: BM=64, BN=128 (full width), BK=16, 256 threads, 4x8 per thread.
// ---------------------------------------------------------------------------
#define BM 64
#define BKK 16

__global__ __launch_bounds__(256) void gemm_relu_kernel(
    const float* __restrict__ A, const float* __restrict__ W,
    const float* __restrict__ b, float* __restrict__ C,
    int M, int K)
{
    __shared__ float As[BKK][BM + 1];   // [k][m], padded
    __shared__ float Bs[BKK][128];

    const int tid  = threadIdx.x;
    const int row0 = blockIdx.x * BM;

    const int ty = tid >> 4;        // 0..15
    const int tx = tid & 15;        // 0..15

    // A-tile load mapping: 64 rows x 16 k, float4 along K
    const int a_row = tid >> 2;             // 0..63
    const int a_k   = (tid & 3) * 4;        // 0,4,8,12
    // B-tile load mapping: 2 float4 per thread
    const int b_r = tid >> 5;               // 0..7
    const int b_c = (tid & 31) * 4;         // 0..124

    float acc[4][8];
#pragma unroll
    for (int i = 0; i < 4; i++)
#pragma unroll
        for (int j = 0; j < 8; j++) acc[i][j] = 0.f;

    float bias[8];
#pragma unroll
    for (int j = 0; j < 8; j++) bias[j] = b[tx + 16 * j];

    const int gr = row0 + a_row;
    for (int k0 = 0; k0 < K; k0 += BKK) {
        float4 av = make_float4(0.f, 0.f, 0.f, 0.f);
        if (gr < M)
            av = *(const float4*)&A[(size_t)gr * K + k0 + a_k];
        As[a_k + 0][a_row] = av.x;
        As[a_k + 1][a_row] = av.y;
        As[a_k + 2][a_row] = av.z;
        As[a_k + 3][a_row] = av.w;

        float4 w0 = *(const float4*)&W[(size_t)(k0 + b_r) * 128 + b_c];
        float4 w1 = *(const float4*)&W[(size_t)(k0 + 8 + b_r) * 128 + b_c];
        *(float4*)&Bs[b_r    ][b_c] = w0;
        *(float4*)&Bs[b_r + 8][b_c] = w1;

        __syncthreads();

#pragma unroll
        for (int k = 0; k < BKK; k++) {
            float a[4], wv[8];
#pragma unroll
            for (int i = 0; i < 4; i++) a[i] = As[k][ty + 16 * i];
#pragma unroll
            for (int j = 0; j < 8; j++) wv[j] = Bs[k][tx + 16 * j];
#pragma unroll
            for (int i = 0; i < 4; i++)
#pragma unroll
                for (int j = 0; j < 8; j++) acc[i][j] += a[i] * wv[j];
        }
        __syncthreads();
    }

#pragma unroll
    for (int i = 0; i < 4; i++) {
        int r = row0 + ty + 16 * i;
        if (r < M) {
#pragma unroll
            for (int j = 0; j < 8; j++) {
                float v = acc[i][j] + bias[j];
                C[(size_t)r * 128 + tx + 16 * j] = v > 0.f ? v : 0.f;
            }
        }
    }
}

// ---------------------------------------------------------------------------
// Edge-parallel scatter SpMM (128-wide rows):
//   out[dst[e], :] += w[e] * x[src[e], :]
// One warp per edge; each lane handles 4 floats via red.global.add.v4.f32.
// ---------------------------------------------------------------------------
__global__ __launch_bounds__(256) void spmm128_scatter_kernel(
    const int* __restrict__ src, const int* __restrict__ dst,
    const float* __restrict__ w, const float* __restrict__ x,
    float* __restrict__ out, int E)
{
    int t = blockIdx.x * blockDim.x + threadIdx.x;
    int e = t >> 5;
    if (e >= E) return;
    int lane = t & 31;

    int   s  = __ldg(&src[e]);
    int   d  = __ldg(&dst[e]);
    float wt = __ldg(&w[e]);

    float4 v = *(const float4*)&x[(size_t)s * 128 + lane * 4];
    v.x *= wt; v.y *= wt; v.z *= wt; v.w *= wt;

    float* p = &out[(size_t)d * 128 + lane * 4];
    asm volatile("red.global.add.v4.f32 [%0], {%1, %2, %3, %4};"
                 :: "l"(p), "f"(v.x), "f"(v.y), "f"(v.z), "f"(v.w)
                 : "memory");
}

// ---------------------------------------------------------------------------
// Final epilogue per doc node n:
//   doc[n]     = [ r0/(|r0|+eps) | [rA|rw]/(|[rA|rw]|+eps) ]          (384)
//   doc_svd[n] = [ r0s/(|r0s|+eps) | [rB|rw]/(|[rB|rw]|+eps) ]       (384)
// out = [doc (10000x384) ; doc_svd (10000x384)]
// ---------------------------------------------------------------------------
__global__ __launch_bounds__(128) void finalize_kernel(
    const float* __restrict__ r0, const float* __restrict__ rA,
    const float* __restrict__ rw, const float* __restrict__ r0s,
    const float* __restrict__ rB, float* __restrict__ out)
{
    const int n = blockIdx.x;
    const int t = threadIdx.x;          // 0..127
    const int lane = t & 31, wid = t >> 5;

    const size_t base = (size_t)n * 128 + t;
    float v0  = r0 [base];
    float vA  = rA [base];
    float vW  = rw [base];
    float v0s = r0s[base];
    float vB  = rB [base];

    float4 sq = make_float4(v0 * v0,
                            vA * vA + vW * vW,
                            v0s * v0s,
                            vB * vB + vW * vW);
#pragma unroll
    for (int o = 16; o; o >>= 1) {
        sq.x += __shfl_xor_sync(0xffffffffu, sq.x, o);
        sq.y += __shfl_xor_sync(0xffffffffu, sq.y, o);
        sq.z += __shfl_xor_sync(0xffffffffu, sq.z, o);
        sq.w += __shfl_xor_sync(0xffffffffu, sq.w, o);
    }
    __shared__ float4 wsum[4];
    if (lane == 0) wsum[wid] = sq;
    __syncthreads();
    float s0  = wsum[0].x + wsum[1].x + wsum[2].x + wsum[3].x;
    float s1  = wsum[0].y + wsum[1].y + wsum[2].y + wsum[3].y;
    float s0s = wsum[0].z + wsum[1].z + wsum[2].z + wsum[3].z;
    float s1s = wsum[0].w + wsum[1].w + wsum[2].w + wsum[3].w;

    const float EPS = 1e-9f;
    float i0  = 1.f / (sqrtf(s0)  + EPS);
    float i1  = 1.f / (sqrtf(s1)  + EPS);
    float i0s = 1.f / (sqrtf(s0s) + EPS);
    float i1s = 1.f / (sqrtf(s1s) + EPS);

    size_t drow = (size_t)n * 384;
    out[drow + t]        = v0 * i0;
    out[drow + 128 + t]  = vA * i1;
    out[drow + 256 + t]  = vW * i1;

    size_t srow = (size_t)N0_DOCS * 384 + drow;
    out[srow + t]        = v0s * i0s;
    out[srow + 128 + t]  = vB * i1s;
    out[srow + 256 + t]  = vW * i1s;
}

// ---------------------------------------------------------------------------
// Launch
// ---------------------------------------------------------------------------
extern "C" void kernel_launch(void* const* d_in, const int* in_sizes, int n_in,
                              void* d_out, int out_size)
{
    const float* x1       = (const float*)d_in[0];
    const float* x2       = (const float*)d_in[1];
    const float* word_emb = (const float*)d_in[2];
    const float* W1a = (const float*)d_in[3];
    const float* b1a = (const float*)d_in[4];
    const float* W1b = (const float*)d_in[5];
    const float* b1b = (const float*)d_in[6];
    const float* W2a = (const float*)d_in[7];
    const float* b2a = (const float*)d_in[8];
    const float* W2b = (const float*)d_in[9];
    const float* b2b = (const float*)d_in[10];
    const int*   e11_src = (const int*)d_in[11];
    const int*   e11_dst = (const int*)d_in[12];
    const float* e11_w   = (const float*)d_in[13];
    const int*   e22_src = (const int*)d_in[14];
    const int*   e22_dst = (const int*)d_in[15];
    const float* e22_w   = (const float*)d_in[16];
    const int*   e01_src = (const int*)d_in[17];
    const int*   e01_dst = (const int*)d_in[18];
    const float* e01_w   = (const float*)d_in[19];
    const int*   e02_src = (const int*)d_in[20];
    const int*   e02_dst = (const int*)d_in[21];
    const float* e02_w   = (const float*)d_in[22];

    const int N1  = in_sizes[0] / 256;
    const int N2  = in_sizes[1] / 256;
    const int E11 = in_sizes[11];
    const int E22 = in_sizes[14];
    const int E01 = in_sizes[17];
    const int E02 = in_sizes[20];

    float *l1_1, *h1, *l2_1, *l1_2, *h2, *l2_2, *r0, *r0s, *rA, *rB, *rw;
    cudaGetSymbolAddress((void**)&l1_1, g_l1_1);
    cudaGetSymbolAddress((void**)&h1,   g_h1);
    cudaGetSymbolAddress((void**)&l2_1, g_l2_1);
    cudaGetSymbolAddress((void**)&l1_2, g_l1_2);
    cudaGetSymbolAddress((void**)&h2,   g_h2);
    cudaGetSymbolAddress((void**)&l2_2, g_l2_2);
    cudaGetSymbolAddress((void**)&r0,   g_r0);
    cudaGetSymbolAddress((void**)&r0s,  g_r0s);
    cudaGetSymbolAddress((void**)&rA,   g_rA);
    cudaGetSymbolAddress((void**)&rB,   g_rB);
    cudaGetSymbolAddress((void**)&rw,   g_rw);

    // Layer 1 (identity GCN): l1_x = relu(x @ Wa + ba)
    gemm_relu_kernel<<<(N1 + BM - 1) / BM, 256>>>(x1, W1a, b1a, l1_1, N1, 256);
    gemm_relu_kernel<<<(N2 + BM - 1) / BM, 256>>>(x2, W2a, b2a, l1_2, N2, 256);

    // h = spmm(e_same_type, l1)
    cudaMemsetAsync(h1, 0, (size_t)N1 * 128 * sizeof(float), 0);
    cudaMemsetAsync(h2, 0, (size_t)N2 * 128 * sizeof(float), 0);
    {
        long long th11 = (long long)E11 * 32;
        spmm128_scatter_kernel<<<(unsigned)((th11 + 255) / 256), 256>>>(
            e11_src, e11_dst, e11_w, l1_1, h1, E11);
        long long th22 = (long long)E22 * 32;
        spmm128_scatter_kernel<<<(unsigned)((th22 + 255) / 256), 256>>>(
            e22_src, e22_dst, e22_w, l1_2, h2, E22);
    }

    // Layer 2: l2_x = relu(h @ Wb + bb)
    gemm_relu_kernel<<<(N1 + BM - 1) / BM, 256>>>(h1, W1b, b1b, l2_1, N1, 128);
    gemm_relu_kernel<<<(N2 + BM - 1) / BM, 256>>>(h2, W2b, b2b, l2_2, N2, 128);

    // Doc-level aggregations (word_emb spmm shared between r1 and r1s)
    size_t docbytes = (size_t)N0_DOCS * 128 * sizeof(float);
    cudaMemsetAsync(r0,  0, docbytes, 0);
    cudaMemsetAsync(r0s, 0, docbytes, 0);
    cudaMemsetAsync(rA,  0, docbytes, 0);
    cudaMemsetAsync(rB,  0, docbytes, 0);
    cudaMemsetAsync(rw,  0, docbytes, 0);

    long long th01 = (long long)E01 * 32;
    long long th02 = (long long)E02 * 32;
    spmm128_scatter_kernel<<<(unsigned)((th01 + 255) / 256), 256>>>(
        e01_src, e01_dst, e01_w, l2_1, r0, E01);
    spmm128_scatter_kernel<<<(unsigned)((th01 + 255) / 256), 256>>>(
        e01_src, e01_dst, e01_w, l1_1, r0s, E01);
    spmm128_scatter_kernel<<<(unsigned)((th02 + 255) / 256), 256>>>(
        e02_src, e02_dst, e02_w, l2_2, rA, E02);
    spmm128_scatter_kernel<<<(unsigned)((th02 + 255) / 256), 256>>>(
        e02_src, e02_dst, e02_w, l1_2, rB, E02);
    spmm128_scatter_kernel<<<(unsigned)((th02 + 255) / 256), 256>>>(
        e02_src, e02_dst, e02_w, word_emb, rw, E02);

    // L2-normalize + concat into d_out: [doc ; doc_svd]
    finalize_kernel<<<N0_DOCS, 128>>>(r0, rA, rw, r0s, rB, (float*)d_out);
}

// round 2
// speedup vs baseline: 1.3185x; 1.3185x over previous
#include <cuda_runtime.h>
#include <math.h>

typedef unsigned long long ull;

#define N0_DOCS 10000
#define MAXN1 50000
#define MAXN2 30000

// Scratch (device globals; no allocation allowed)
__device__ float g_l1_1[MAXN1 * 128];
__device__ float g_h1  [MAXN1 * 128];
__device__ float g_l2_1[MAXN1 * 128];
__device__ float g_l1_2[MAXN2 * 128];
__device__ float g_h2  [MAXN2 * 128];
__device__ float g_l2_2[MAXN2 * 128];
__device__ float g_r0 [N0_DOCS * 128];
__device__ float g_r0s[N0_DOCS * 128];
__device__ float g_rA [N0_DOCS * 128];
__device__ float g_rB [N0_DOCS * 128];
__device__ float g_rw [N0_DOCS * 128];

// ---------------------------------------------------------------------------
// Packed f32x2 helpers (sm_100+ PTX)
// ---------------------------------------------------------------------------
__device__ __forceinline__ ull splat2(float x) {
    ull r;
    asm("mov.b64 %0, {%1, %1};" : "=l"(r) : "f"(x));
    return r;
}
__device__ __forceinline__ ull ffma2(ull a, ull b, ull c) {
    ull d;
    asm("fma.rn.f32x2 %0, %1, %2, %3;" : "=l"(d) : "l"(a), "l"(b), "l"(c));
    return d;
}
__device__ __forceinline__ float2 unpack2(ull v) {
    float2 r;
    asm("mov.b64 {%0, %1}, %2;" : "=f"(r.x), "=f"(r.y) : "l"(v));
    return r;
}

// ---------------------------------------------------------------------------
// GEMM + bias + ReLU:  C[M,128] = relu(A[M,K] @ W[K,128] + b)
// 128x128 tile, BK=8, 256 threads, 8x8 per thread, packed f32x2 FMA.
// acc pairs run along M (loaded pre-packed from SMEM with LDS.128).
// ---------------------------------------------------------------------------
#define TM 128
#define TK 8

__global__ __launch_bounds__(256) void gemm128_relu_kernel(
    const float* __restrict__ A, const float* __restrict__ W,
    const float* __restrict__ bias, float* __restrict__ C,
    int M, int K)
{
    __shared__ float As[TK][TM];    // [k][m]
    __shared__ float Bs[TK][128];   // [k][n]

    const int tid  = threadIdx.x;
    const int tx   = tid & 15;      // n-group: cols tx*8 .. tx*8+7
    const int ty   = tid >> 4;      // m-group: rows ty*8 .. ty*8+7
    const int row0 = blockIdx.x * TM;

    // A staging: 256 threads x 1 float4 = 128 rows x 8 k
    const int am = tid >> 1;            // 0..127
    const int ak = (tid & 1) * 4;       // 0 or 4
    // B staging: 8 k x 128 n
    const int bk = tid >> 5;            // 0..7
    const int bn = (tid & 31) * 4;      // 0..124

    ull acc[4][8];  // 4 m-pairs x 8 n
#pragma unroll
    for (int p = 0; p < 4; p++)
#pragma unroll
        for (int n = 0; n < 8; n++) acc[p][n] = 0ULL;

    const int gr = row0 + am;
    for (int k0 = 0; k0 < K; k0 += TK) {
        float4 av = make_float4(0.f, 0.f, 0.f, 0.f);
        if (gr < M)
            av = *(const float4*)&A[(size_t)gr * K + k0 + ak];
        As[ak + 0][am] = av.x;
        As[ak + 1][am] = av.y;
        As[ak + 2][am] = av.z;
        As[ak + 3][am] = av.w;

        *(float4*)&Bs[bk][bn] = *(const float4*)&W[(size_t)(k0 + bk) * 128 + bn];
        __syncthreads();

#pragma unroll
        for (int kk = 0; kk < TK; kk++) {
            // A m-pairs, pre-packed in shared memory order
            union { float4 f; ull u[2]; } a0, a1;
            a0.f = *(const float4*)&As[kk][ty * 8];
            a1.f = *(const float4*)&As[kk][ty * 8 + 4];
            ull ap[4] = {a0.u[0], a0.u[1], a1.u[0], a1.u[1]};

            float4 bv0 = *(const float4*)&Bs[kk][tx * 8];
            float4 bv1 = *(const float4*)&Bs[kk][tx * 8 + 4];
            ull bs[8];
            bs[0] = splat2(bv0.x); bs[1] = splat2(bv0.y);
            bs[2] = splat2(bv0.z); bs[3] = splat2(bv0.w);
            bs[4] = splat2(bv1.x); bs[5] = splat2(bv1.y);
            bs[6] = splat2(bv1.z); bs[7] = splat2(bv1.w);

#pragma unroll
            for (int p = 0; p < 4; p++)
#pragma unroll
                for (int n = 0; n < 8; n++)
                    acc[p][n] = ffma2(ap[p], bs[n], acc[p][n]);
        }
        __syncthreads();
    }

    // Epilogue: unpack, bias, relu, store (2 float4 per row, 8 rows)
    float bvals[8];
#pragma unroll
    for (int n = 0; n < 8; n++) bvals[n] = bias[tx * 8 + n];

#pragma unroll
    for (int p = 0; p < 4; p++) {
        float2 col[8];
#pragma unroll
        for (int n = 0; n < 8; n++) col[n] = unpack2(acc[p][n]);

        int r_lo = row0 + ty * 8 + 2 * p;
        if (r_lo < M) {
            float4 o0, o1;
            o0.x = fmaxf(col[0].x + bvals[0], 0.f);
            o0.y = fmaxf(col[1].x + bvals[1], 0.f);
            o0.z = fmaxf(col[2].x + bvals[2], 0.f);
            o0.w = fmaxf(col[3].x + bvals[3], 0.f);
            o1.x = fmaxf(col[4].x + bvals[4], 0.f);
            o1.y = fmaxf(col[5].x + bvals[5], 0.f);
            o1.z = fmaxf(col[6].x + bvals[6], 0.f);
            o1.w = fmaxf(col[7].x + bvals[7], 0.f);
            *(float4*)&C[(size_t)r_lo * 128 + tx * 8]     = o0;
            *(float4*)&C[(size_t)r_lo * 128 + tx * 8 + 4] = o1;
        }
        int r_hi = r_lo + 1;
        if (r_hi < M) {
            float4 o0, o1;
            o0.x = fmaxf(col[0].y + bvals[0], 0.f);
            o0.y = fmaxf(col[1].y + bvals[1], 0.f);
            o0.z = fmaxf(col[2].y + bvals[2], 0.f);
            o0.w = fmaxf(col[3].y + bvals[3], 0.f);
            o1.x = fmaxf(col[4].y + bvals[4], 0.f);
            o1.y = fmaxf(col[5].y + bvals[5], 0.f);
            o1.z = fmaxf(col[6].y + bvals[6], 0.f);
            o1.w = fmaxf(col[7].y + bvals[7], 0.f);
            *(float4*)&C[(size_t)r_hi * 128 + tx * 8]     = o0;
            *(float4*)&C[(size_t)r_hi * 128 + tx * 8 + 4] = o1;
        }
    }
}

// ---------------------------------------------------------------------------
// Scatter SpMM variants (one warp per edge, red.global.add.v4.f32)
// ---------------------------------------------------------------------------
__device__ __forceinline__ void red_v4(float* p, float4 v) {
    asm volatile("red.global.add.v4.f32 [%0], {%1, %2, %3, %4};"
                 :: "l"(p), "f"(v.x), "f"(v.y), "f"(v.z), "f"(v.w)
                 : "memory");
}
__device__ __forceinline__ float4 scale4(float4 v, float w) {
    v.x *= w; v.y *= w; v.z *= w; v.w *= w; return v;
}

__global__ __launch_bounds__(256) void spmm128_scatter_kernel(
    const int* __restrict__ src, const int* __restrict__ dst,
    const float* __restrict__ w, const float* __restrict__ x,
    float* __restrict__ out, int E)
{
    int t = blockIdx.x * blockDim.x + threadIdx.x;
    int e = t >> 5;
    if (e >= E) return;
    int lane = t & 31;

    int   s  = __ldg(&src[e]);
    int   d  = __ldg(&dst[e]);
    float wt = __ldg(&w[e]);

    float4 v = *(const float4*)&x[(size_t)s * 128 + lane * 4];
    red_v4(&out[(size_t)d * 128 + lane * 4], scale4(v, wt));
}

__global__ __launch_bounds__(256) void spmm128_scatter2_kernel(
    const int* __restrict__ src, const int* __restrict__ dst,
    const float* __restrict__ w,
    const float* __restrict__ x0, const float* __restrict__ x1,
    float* __restrict__ o0, float* __restrict__ o1, int E)
{
    int t = blockIdx.x * blockDim.x + threadIdx.x;
    int e = t >> 5;
    if (e >= E) return;
    int lane = t & 31;

    int   s  = __ldg(&src[e]);
    int   d  = __ldg(&dst[e]);
    float wt = __ldg(&w[e]);

    size_t so = (size_t)s * 128 + lane * 4;
    size_t dofs = (size_t)d * 128 + lane * 4;
    float4 v0 = *(const float4*)&x0[so];
    float4 v1 = *(const float4*)&x1[so];
    red_v4(&o0[dofs], scale4(v0, wt));
    red_v4(&o1[dofs], scale4(v1, wt));
}

__global__ __launch_bounds__(256) void spmm128_scatter3_kernel(
    const int* __restrict__ src, const int* __restrict__ dst,
    const float* __restrict__ w,
    const float* __restrict__ x0, const float* __restrict__ x1,
    const float* __restrict__ x2,
    float* __restrict__ o0, float* __restrict__ o1, float* __restrict__ o2,
    int E)
{
    int t = blockIdx.x * blockDim.x + threadIdx.x;
    int e = t >> 5;
    if (e >= E) return;
    int lane = t & 31;

    int   s  = __ldg(&src[e]);
    int   d  = __ldg(&dst[e]);
    float wt = __ldg(&w[e]);

    size_t so = (size_t)s * 128 + lane * 4;
    size_t dofs = (size_t)d * 128 + lane * 4;
    float4 v0 = *(const float4*)&x0[so];
    float4 v1 = *(const float4*)&x1[so];
    float4 v2 = *(const float4*)&x2[so];
    red_v4(&o0[dofs], scale4(v0, wt));
    red_v4(&o1[dofs], scale4(v1, wt));
    red_v4(&o2[dofs], scale4(v2, wt));
}

// ---------------------------------------------------------------------------
// Final epilogue (l2norm + concat), out = [doc (10000x384) ; doc_svd]
// ---------------------------------------------------------------------------
__global__ __launch_bounds__(128) void finalize_kernel(
    const float* __restrict__ r0, const float* __restrict__ rA,
    const float* __restrict__ rw, const float* __restrict__ r0s,
    const float* __restrict__ rB, float* __restrict__ out)
{
    const int n = blockIdx.x;
    const int t = threadIdx.x;
    const int lane = t & 31, wid = t >> 5;

    const size_t base = (size_t)n * 128 + t;
    float v0  = r0 [base];
    float vA  = rA [base];
    float vW  = rw [base];
    float v0s = r0s[base];
    float vB  = rB [base];

    float4 sq = make_float4(v0 * v0,
                            vA * vA + vW * vW,
                            v0s * v0s,
                            vB * vB + vW * vW);
#pragma unroll
    for (int o = 16; o; o >>= 1) {
        sq.x += __shfl_xor_sync(0xffffffffu, sq.x, o);
        sq.y += __shfl_xor_sync(0xffffffffu, sq.y, o);
        sq.z += __shfl_xor_sync(0xffffffffu, sq.z, o);
        sq.w += __shfl_xor_sync(0xffffffffu, sq.w, o);
    }
    __shared__ float4 wsum[4];
    if (lane == 0) wsum[wid] = sq;
    __syncthreads();
    float s0  = wsum[0].x + wsum[1].x + wsum[2].x + wsum[3].x;
    float s1  = wsum[0].y + wsum[1].y + wsum[2].y + wsum[3].y;
    float s0s = wsum[0].z + wsum[1].z + wsum[2].z + wsum[3].z;
    float s1s = wsum[0].w + wsum[1].w + wsum[2].w + wsum[3].w;

    const float EPS = 1e-9f;
    float i0  = 1.f / (sqrtf(s0)  + EPS);
    float i1  = 1.f / (sqrtf(s1)  + EPS);
    float i0s = 1.f / (sqrtf(s0s) + EPS);
    float i1s = 1.f / (sqrtf(s1s) + EPS);

    size_t drow = (size_t)n * 384;
    out[drow + t]       = v0 * i0;
    out[drow + 128 + t] = vA * i1;
    out[drow + 256 + t] = vW * i1;

    size_t srow = (size_t)N0_DOCS * 384 + drow;
    out[srow + t]       = v0s * i0s;
    out[srow + 128 + t] = vB * i1s;
    out[srow + 256 + t] = vW * i1s;
}

// ---------------------------------------------------------------------------
// Launch: two forked streams (type-1 / type-2 pipelines), join for finalize.
// ---------------------------------------------------------------------------
extern "C" void kernel_launch(void* const* d_in, const int* in_sizes, int n_in,
                              void* d_out, int out_size)
{
    const float* x1       = (const float*)d_in[0];
    const float* x2       = (const float*)d_in[1];
    const float* word_emb = (const float*)d_in[2];
    const float* W1a = (const float*)d_in[3];
    const float* b1a = (const float*)d_in[4];
    const float* W1b = (const float*)d_in[5];
    const float* b1b = (const float*)d_in[6];
    const float* W2a = (const float*)d_in[7];
    const float* b2a = (const float*)d_in[8];
    const float* W2b = (const float*)d_in[9];
    const float* b2b = (const float*)d_in[10];
    const int*   e11_src = (const int*)d_in[11];
    const int*   e11_dst = (const int*)d_in[12];
    const float* e11_w   = (const float*)d_in[13];
    const int*   e22_src = (const int*)d_in[14];
    const int*   e22_dst = (const int*)d_in[15];
    const float* e22_w   = (const float*)d_in[16];
    const int*   e01_src = (const int*)d_in[17];
    const int*   e01_dst = (const int*)d_in[18];
    const float* e01_w   = (const float*)d_in[19];
    const int*   e02_src = (const int*)d_in[20];
    const int*   e02_dst = (const int*)d_in[21];
    const float* e02_w   = (const float*)d_in[22];

    const int N1  = in_sizes[0] / 256;
    const int N2  = in_sizes[1] / 256;
    const int E11 = in_sizes[11];
    const int E22 = in_sizes[14];
    const int E01 = in_sizes[17];
    const int E02 = in_sizes[20];

    float *l1_1, *h1, *l2_1, *l1_2, *h2, *l2_2, *r0, *r0s, *rA, *rB, *rw;
    cudaGetSymbolAddress((void**)&l1_1, g_l1_1);
    cudaGetSymbolAddress((void**)&h1,   g_h1);
    cudaGetSymbolAddress((void**)&l2_1, g_l2_1);
    cudaGetSymbolAddress((void**)&l1_2, g_l1_2);
    cudaGetSymbolAddress((void**)&h2,   g_h2);
    cudaGetSymbolAddress((void**)&l2_2, g_l2_2);
    cudaGetSymbolAddress((void**)&r0,   g_r0);
    cudaGetSymbolAddress((void**)&r0s,  g_r0s);
    cudaGetSymbolAddress((void**)&rA,   g_rA);
    cudaGetSymbolAddress((void**)&rB,   g_rB);
    cudaGetSymbolAddress((void**)&rw,   g_rw);

    static cudaStream_t s1 = nullptr, s2 = nullptr;
    static cudaEvent_t  ev0 = nullptr, ev1 = nullptr, ev2 = nullptr;
    if (s1 == nullptr) {
        cudaStreamCreateWithFlags(&s1, cudaStreamNonBlocking);
        cudaStreamCreateWithFlags(&s2, cudaStreamNonBlocking);
        cudaEventCreateWithFlags(&ev0, cudaEventDisableTiming);
        cudaEventCreateWithFlags(&ev1, cudaEventDisableTiming);
        cudaEventCreateWithFlags(&ev2, cudaEventDisableTiming);
    }

    const size_t docbytes = (size_t)N0_DOCS * 128 * sizeof(float);

    // Fork both pipelines off the capture (default) stream.
    cudaEventRecord(ev0, 0);
    cudaStreamWaitEvent(s1, ev0, 0);
    cudaStreamWaitEvent(s2, ev0, 0);

    // ---- stream 1: type-1 pipeline ----
    cudaMemsetAsync(h1,  0, (size_t)N1 * 128 * sizeof(float), s1);
    cudaMemsetAsync(r0,  0, docbytes, s1);
    cudaMemsetAsync(r0s, 0, docbytes, s1);
    gemm128_relu_kernel<<<(N1 + TM - 1) / TM, 256, 0, s1>>>(x1, W1a, b1a, l1_1, N1, 256);
    spmm128_scatter_kernel<<<(unsigned)(((long long)E11 * 32 + 255) / 256), 256, 0, s1>>>(
        e11_src, e11_dst, e11_w, l1_1, h1, E11);
    gemm128_relu_kernel<<<(N1 + TM - 1) / TM, 256, 0, s1>>>(h1, W1b, b1b, l2_1, N1, 128);
    spmm128_scatter2_kernel<<<(unsigned)(((long long)E01 * 32 + 255) / 256), 256, 0, s1>>>(
        e01_src, e01_dst, e01_w, l2_1, l1_1, r0, r0s, E01);
    cudaEventRecord(ev1, s1);

    // ---- stream 2: type-2 pipeline ----
    cudaMemsetAsync(h2, 0, (size_t)N2 * 128 * sizeof(float), s2);
    cudaMemsetAsync(rA, 0, docbytes, s2);
    cudaMemsetAsync(rB, 0, docbytes, s2);
    cudaMemsetAsync(rw, 0, docbytes, s2);
    gemm128_relu_kernel<<<(N2 + TM - 1) / TM, 256, 0, s2>>>(x2, W2a, b2a, l1_2, N2, 256);
    spmm128_scatter_kernel<<<(unsigned)(((long long)E22 * 32 + 255) / 256), 256, 0, s2>>>(
        e22_src, e22_dst, e22_w, l1_2, h2, E22);
    gemm128_relu_kernel<<<(N2 + TM - 1) / TM, 256, 0, s2>>>(h2, W2b, b2b, l2_2, N2, 128);
    spmm128_scatter3_kernel<<<(unsigned)(((long long)E02 * 32 + 255) / 256), 256, 0, s2>>>(
        e02_src, e02_dst, e02_w, l2_2, l1_2, word_emb, rA, rB, rw, E02);
    cudaEventRecord(ev2, s2);

    // ---- join + finalize ----
    cudaStreamWaitEvent(0, ev1, 0);
    cudaStreamWaitEvent(0, ev2, 0);
    finalize_kernel<<<N0_DOCS, 128, 0, 0>>>(r0, rA, rw, r0s, rB, (float*)d_out);
}

// round 4
// speedup vs baseline: 1.8499x; 1.4030x over previous
#include <cuda_runtime.h>
#include <math.h>

typedef unsigned long long ull;

#define N0_DOCS 10000
#define MAXN1 50000
#define MAXN2 30000
#define NTOT (MAXN1 + MAXN2 + 2 * N0_DOCS)      // 100000
#define ETOT (800000 + 480000 + 320000 + 160000) // 1760000

// ---------------- feature scratch ----------------
__device__ float g_l1_1[MAXN1 * 128];
__device__ float g_h1  [MAXN1 * 128];
__device__ float g_l2_1[MAXN1 * 128];
__device__ float g_l1_2[MAXN2 * 128];
__device__ float g_h2  [MAXN2 * 128];
__device__ float g_l2_2[MAXN2 * 128];
__device__ float g_r0 [N0_DOCS * 128];
__device__ float g_r0s[N0_DOCS * 128];
__device__ float g_rA [N0_DOCS * 128];
__device__ float g_rB [N0_DOCS * 128];
__device__ float g_rw [N0_DOCS * 128];

// ---------------- CSR scratch (concatenated across all 4 graphs) ----------------
__device__ int   g_cntfc[2 * NTOT];   // [0:NTOT)=cnt, [NTOT:2*NTOT)=fc
__device__ int   g_ptr[NTOT];
__device__ int   g_ci[ETOT];
__device__ float g_wv[ETOT];
__device__ int   g_bsum[128];

// ---------------------------------------------------------------------------
// Packed f32x2 helpers
// ---------------------------------------------------------------------------
__device__ __forceinline__ ull splat2(float x) {
    ull r; asm("mov.b64 %0, {%1, %1};" : "=l"(r) : "f"(x)); return r;
}
__device__ __forceinline__ ull ffma2(ull a, ull b, ull c) {
    ull d; asm("fma.rn.f32x2 %0, %1, %2, %3;" : "=l"(d) : "l"(a), "l"(b), "l"(c)); return d;
}
__device__ __forceinline__ float2 unpack2(ull v) {
    float2 r; asm("mov.b64 {%0, %1}, %2;" : "=f"(r.x), "=f"(r.y) : "l"(v)); return r;
}

// ---------------------------------------------------------------------------
// GEMM + bias + ReLU (128x128 tile, BK=8, 256 threads, f32x2 FMA)
// ---------------------------------------------------------------------------
#define TM 128
#define TK 8

__global__ __launch_bounds__(256) void gemm128_relu_kernel(
    const float* __restrict__ A, const float* __restrict__ W,
    const float* __restrict__ bias, float* __restrict__ C,
    int M, int K)
{
    __shared__ float As[TK][TM];
    __shared__ float Bs[TK][128];

    const int tid  = threadIdx.x;
    const int tx   = tid & 15;
    const int ty   = tid >> 4;
    const int row0 = blockIdx.x * TM;

    const int am = tid >> 1;
    const int ak = (tid & 1) * 4;
    const int bk = tid >> 5;
    const int bn = (tid & 31) * 4;

    ull acc[4][8];
#pragma unroll
    for (int p = 0; p < 4; p++)
#pragma unroll
        for (int n = 0; n < 8; n++) acc[p][n] = 0ULL;

    const int gr = row0 + am;
    for (int k0 = 0; k0 < K; k0 += TK) {
        float4 av = make_float4(0.f, 0.f, 0.f, 0.f);
        if (gr < M)
            av = *(const float4*)&A[(size_t)gr * K + k0 + ak];
        As[ak + 0][am] = av.x;
        As[ak + 1][am] = av.y;
        As[ak + 2][am] = av.z;
        As[ak + 3][am] = av.w;

        *(float4*)&Bs[bk][bn] = *(const float4*)&W[(size_t)(k0 + bk) * 128 + bn];
        __syncthreads();

#pragma unroll
        for (int kk = 0; kk < TK; kk++) {
            union { float4 f; ull u[2]; } a0, a1;
            a0.f = *(const float4*)&As[kk][ty * 8];
            a1.f = *(const float4*)&As[kk][ty * 8 + 4];
            ull ap[4] = {a0.u[0], a0.u[1], a1.u[0], a1.u[1]};

            float4 bv0 = *(const float4*)&Bs[kk][tx * 8];
            float4 bv1 = *(const float4*)&Bs[kk][tx * 8 + 4];
            ull bs[8];
            bs[0] = splat2(bv0.x); bs[1] = splat2(bv0.y);
            bs[2] = splat2(bv0.z); bs[3] = splat2(bv0.w);
            bs[4] = splat2(bv1.x); bs[5] = splat2(bv1.y);
            bs[6] = splat2(bv1.z); bs[7] = splat2(bv1.w);

#pragma unroll
            for (int p = 0; p < 4; p++)
#pragma unroll
                for (int n = 0; n < 8; n++)
                    acc[p][n] = ffma2(ap[p], bs[n], acc[p][n]);
        }
        __syncthreads();
    }

    float bvals[8];
#pragma unroll
    for (int n = 0; n < 8; n++) bvals[n] = bias[tx * 8 + n];

#pragma unroll
    for (int p = 0; p < 4; p++) {
        float2 col[8];
#pragma unroll
        for (int n = 0; n < 8; n++) col[n] = unpack2(acc[p][n]);

        int r_lo = row0 + ty * 8 + 2 * p;
        if (r_lo < M) {
            float4 o0, o1;
            o0.x = fmaxf(col[0].x + bvals[0], 0.f);
            o0.y = fmaxf(col[1].x + bvals[1], 0.f);
            o0.z = fmaxf(col[2].x + bvals[2], 0.f);
            o0.w = fmaxf(col[3].x + bvals[3], 0.f);
            o1.x = fmaxf(col[4].x + bvals[4], 0.f);
            o1.y = fmaxf(col[5].x + bvals[5], 0.f);
            o1.z = fmaxf(col[6].x + bvals[6], 0.f);
            o1.w = fmaxf(col[7].x + bvals[7], 0.f);
            *(float4*)&C[(size_t)r_lo * 128 + tx * 8]     = o0;
            *(float4*)&C[(size_t)r_lo * 128 + tx * 8 + 4] = o1;
        }
        int r_hi = r_lo + 1;
        if (r_hi < M) {
            float4 o0, o1;
            o0.x = fmaxf(col[0].y + bvals[0], 0.f);
            o0.y = fmaxf(col[1].y + bvals[1], 0.f);
            o0.z = fmaxf(col[2].y + bvals[2], 0.f);
            o0.w = fmaxf(col[3].y + bvals[3], 0.f);
            o1.x = fmaxf(col[4].y + bvals[4], 0.f);
            o1.y = fmaxf(col[5].y + bvals[5], 0.f);
            o1.z = fmaxf(col[6].y + bvals[6], 0.f);
            o1.w = fmaxf(col[7].y + bvals[7], 0.f);
            *(float4*)&C[(size_t)r_hi * 128 + tx * 8]     = o0;
            *(float4*)&C[(size_t)r_hi * 128 + tx * 8 + 4] = o1;
        }
    }
}

// ---------------------------------------------------------------------------
// Fused CSR build across all 4 graphs (concatenated node space)
// ---------------------------------------------------------------------------
__global__ __launch_bounds__(256) void hist_all_kernel(
    const int* __restrict__ d11, const int* __restrict__ d22,
    const int* __restrict__ d01, const int* __restrict__ d02,
    int E11, int E22, int E01, int E02,
    int b22, int b01, int b02,
    int* __restrict__ cnt)
{
    int i = blockIdx.x * blockDim.x + threadIdx.x;
    int E12 = E11 + E22, E123 = E12 + E01, E = E123 + E02;
    if (i >= E) return;
    int node;
    if (i < E11)       node =        d11[i];
    else if (i < E12)  node = b22 +  d22[i - E11];
    else if (i < E123) node = b01 +  d01[i - E12];
    else               node = b02 +  d02[i - E123];
    atomicAdd(&cnt[node], 1);
}

#define SCB 1024
__global__ __launch_bounds__(SCB) void scan1_kernel(
    const int* __restrict__ in, int* __restrict__ out, int* __restrict__ bsum, int n)
{
    __shared__ int sh[SCB];
    int i = blockIdx.x * SCB + threadIdx.x;
    int v = (i < n) ? in[i] : 0;
    sh[threadIdx.x] = v;
    __syncthreads();
#pragma unroll
    for (int o = 1; o < SCB; o <<= 1) {
        int t = (threadIdx.x >= o) ? sh[threadIdx.x - o] : 0;
        __syncthreads();
        sh[threadIdx.x] += t;
        __syncthreads();
    }
    if (i < n) out[i] = sh[threadIdx.x] - v;
    if (threadIdx.x == SCB - 1) bsum[blockIdx.x] = sh[threadIdx.x];
}

__global__ __launch_bounds__(SCB) void scan2_kernel(int* __restrict__ bsum, int nb)
{
    __shared__ int sh[SCB];
    int v = (threadIdx.x < nb) ? bsum[threadIdx.x] : 0;
    sh[threadIdx.x] = v;
    __syncthreads();
#pragma unroll
    for (int o = 1; o < SCB; o <<= 1) {
        int t = (threadIdx.x >= o) ? sh[threadIdx.x - o] : 0;
        __syncthreads();
        sh[threadIdx.x] += t;
        __syncthreads();
    }
    if (threadIdx.x < nb) bsum[threadIdx.x] = sh[threadIdx.x] - v;
}

__global__ __launch_bounds__(SCB) void scan3_kernel(
    int* __restrict__ out, const int* __restrict__ bsum, int n)
{
    int i = blockIdx.x * SCB + threadIdx.x;
    if (i < n) out[i] += bsum[blockIdx.x];
}

__global__ __launch_bounds__(256) void fill_all_kernel(
    const int* __restrict__ s11, const int* __restrict__ d11, const float* __restrict__ w11,
    const int* __restrict__ s22, const int* __restrict__ d22, const float* __restrict__ w22,
    const int* __restrict__ s01, const int* __restrict__ d01, const float* __restrict__ w01,
    const int* __restrict__ s02, const int* __restrict__ d02, const float* __restrict__ w02,
    int E11, int E22, int E01, int E02,
    int b22, int b01, int b02,
    const int* __restrict__ ptr, int* __restrict__ fc,
    int* __restrict__ ci, float* __restrict__ wv)
{
    int i = blockIdx.x * blockDim.x + threadIdx.x;
    int E12 = E11 + E22, E123 = E12 + E01, E = E123 + E02;
    if (i >= E) return;
    int node, s; float w;
    if (i < E11)       { node =       d11[i];        s = s11[i];        w = w11[i]; }
    else if (i < E12)  { int j = i - E11;  node = b22 + d22[j]; s = s22[j]; w = w22[j]; }
    else if (i < E123) { int j = i - E12;  node = b01 + d01[j]; s = s01[j]; w = w01[j]; }
    else               { int j = i - E123; node = b02 + d02[j]; s = s02[j]; w = w02[j]; }
    int pos = ptr[node] + atomicAdd(&fc[node], 1);
    ci[pos] = s;
    wv[pos] = w;
}

// ---------------------------------------------------------------------------
// Gather SpMM kernels (one warp per dst node; global CSR offsets)
// ---------------------------------------------------------------------------
__global__ __launch_bounds__(256) void gather1_kernel(
    const int* __restrict__ ptr, const int* __restrict__ cnt,
    const int* __restrict__ ci, const float* __restrict__ wv,
    const float* __restrict__ x, float* __restrict__ out, int N)
{
    int t = blockIdx.x * blockDim.x + threadIdx.x;
    int n = t >> 5;
    if (n >= N) return;
    int lane = t & 31;

    int beg = __ldg(&ptr[n]);
    int end = beg + __ldg(&cnt[n]);
    float4 acc = make_float4(0.f, 0.f, 0.f, 0.f);

    int e = beg;
    for (; e + 4 <= end; e += 4) {
        int s0 = __ldg(&ci[e]),   s1 = __ldg(&ci[e+1]);
        int s2 = __ldg(&ci[e+2]), s3 = __ldg(&ci[e+3]);
        float w0 = __ldg(&wv[e]),   w1 = __ldg(&wv[e+1]);
        float w2 = __ldg(&wv[e+2]), w3 = __ldg(&wv[e+3]);
        float4 v0 = *(const float4*)&x[(size_t)s0 * 128 + lane * 4];
        float4 v1 = *(const float4*)&x[(size_t)s1 * 128 + lane * 4];
        float4 v2 = *(const float4*)&x[(size_t)s2 * 128 + lane * 4];
        float4 v3 = *(const float4*)&x[(size_t)s3 * 128 + lane * 4];
        acc.x = fmaf(w0, v0.x, fmaf(w1, v1.x, fmaf(w2, v2.x, fmaf(w3, v3.x, acc.x))));
        acc.y = fmaf(w0, v0.y, fmaf(w1, v1.y, fmaf(w2, v2.y, fmaf(w3, v3.y, acc.y))));
        acc.z = fmaf(w0, v0.z, fmaf(w1, v1.z, fmaf(w2, v2.z, fmaf(w3, v3.z, acc.z))));
        acc.w = fmaf(w0, v0.w, fmaf(w1, v1.w, fmaf(w2, v2.w, fmaf(w3, v3.w, acc.w))));
    }
    for (; e < end; e++) {
        int s = __ldg(&ci[e]);
        float w0 = __ldg(&wv[e]);
        float4 v = *(const float4*)&x[(size_t)s * 128 + lane * 4];
        acc.x = fmaf(w0, v.x, acc.x);
        acc.y = fmaf(w0, v.y, acc.y);
        acc.z = fmaf(w0, v.z, acc.z);
        acc.w = fmaf(w0, v.w, acc.w);
    }
    *(float4*)&out[(size_t)n * 128 + lane * 4] = acc;
}

__global__ __launch_bounds__(256) void gather2_kernel(
    const int* __restrict__ ptr, const int* __restrict__ cnt,
    const int* __restrict__ ci, const float* __restrict__ wv,
    const float* __restrict__ x0, const float* __restrict__ x1,
    float* __restrict__ o0, float* __restrict__ o1, int N)
{
    int t = blockIdx.x * blockDim.x + threadIdx.x;
    int n = t >> 5;
    if (n >= N) return;
    int lane = t & 31;

    int beg = __ldg(&ptr[n]);
    int end = beg + __ldg(&cnt[n]);
    float4 a0 = make_float4(0.f, 0.f, 0.f, 0.f);
    float4 a1 = a0;

    int e = beg;
    for (; e + 2 <= end; e += 2) {
        int sA = __ldg(&ci[e]), sB = __ldg(&ci[e+1]);
        float wA = __ldg(&wv[e]), wB = __ldg(&wv[e+1]);
        size_t oA = (size_t)sA * 128 + lane * 4;
        size_t oB = (size_t)sB * 128 + lane * 4;
        float4 vA0 = *(const float4*)&x0[oA];
        float4 vB0 = *(const float4*)&x0[oB];
        float4 vA1 = *(const float4*)&x1[oA];
        float4 vB1 = *(const float4*)&x1[oB];
        a0.x = fmaf(wA, vA0.x, fmaf(wB, vB0.x, a0.x));
        a0.y = fmaf(wA, vA0.y, fmaf(wB, vB0.y, a0.y));
        a0.z = fmaf(wA, vA0.z, fmaf(wB, vB0.z, a0.z));
        a0.w = fmaf(wA, vA0.w, fmaf(wB, vB0.w, a0.w));
        a1.x = fmaf(wA, vA1.x, fmaf(wB, vB1.x, a1.x));
        a1.y = fmaf(wA, vA1.y, fmaf(wB, vB1.y, a1.y));
        a1.z = fmaf(wA, vA1.z, fmaf(wB, vB1.z, a1.z));
        a1.w = fmaf(wA, vA1.w, fmaf(wB, vB1.w, a1.w));
    }
    for (; e < end; e++) {
        int s = __ldg(&ci[e]);
        float w0 = __ldg(&wv[e]);
        size_t o = (size_t)s * 128 + lane * 4;
        float4 v0 = *(const float4*)&x0[o];
        float4 v1 = *(const float4*)&x1[o];
        a0.x = fmaf(w0, v0.x, a0.x); a0.y = fmaf(w0, v0.y, a0.y);
        a0.z = fmaf(w0, v0.z, a0.z); a0.w = fmaf(w0, v0.w, a0.w);
        a1.x = fmaf(w0, v1.x, a1.x); a1.y = fmaf(w0, v1.y, a1.y);
        a1.z = fmaf(w0, v1.z, a1.z); a1.w = fmaf(w0, v1.w, a1.w);
    }
    size_t od = (size_t)n * 128 + lane * 4;
    *(float4*)&o0[od] = a0;
    *(float4*)&o1[od] = a1;
}

__global__ __launch_bounds__(256) void gather3_kernel(
    const int* __restrict__ ptr, const int* __restrict__ cnt,
    const int* __restrict__ ci, const float* __restrict__ wv,
    const float* __restrict__ x0, const float* __restrict__ x1,
    const float* __restrict__ x2,
    float* __restrict__ o0, float* __restrict__ o1, float* __restrict__ o2, int N)
{
    int t = blockIdx.x * blockDim.x + threadIdx.x;
    int n = t >> 5;
    if (n >= N) return;
    int lane = t & 31;

    int beg = __ldg(&ptr[n]);
    int end = beg + __ldg(&cnt[n]);
    float4 a0 = make_float4(0.f, 0.f, 0.f, 0.f);
    float4 a1 = a0, a2 = a0;

    int e = beg;
    for (; e + 2 <= end; e += 2) {
        int sA = __ldg(&ci[e]), sB = __ldg(&ci[e+1]);
        float wA = __ldg(&wv[e]), wB = __ldg(&wv[e+1]);
        size_t oA = (size_t)sA * 128 + lane * 4;
        size_t oB = (size_t)sB * 128 + lane * 4;
        float4 vA0 = *(const float4*)&x0[oA];
        float4 vB0 = *(const float4*)&x0[oB];
        float4 vA1 = *(const float4*)&x1[oA];
        float4 vB1 = *(const float4*)&x1[oB];
        float4 vA2 = *(const float4*)&x2[oA];
        float4 vB2 = *(const float4*)&x2[oB];
        a0.x = fmaf(wA, vA0.x, fmaf(wB, vB0.x, a0.x));
        a0.y = fmaf(wA, vA0.y, fmaf(wB, vB0.y, a0.y));
        a0.z = fmaf(wA, vA0.z, fmaf(wB, vB0.z, a0.z));
        a0.w = fmaf(wA, vA0.w, fmaf(wB, vB0.w, a0.w));
        a1.x = fmaf(wA, vA1.x, fmaf(wB, vB1.x, a1.x));
        a1.y = fmaf(wA, vA1.y, fmaf(wB, vB1.y, a1.y));
        a1.z = fmaf(wA, vA1.z, fmaf(wB, vB1.z, a1.z));
        a1.w = fmaf(wA, vA1.w, fmaf(wB, vB1.w, a1.w));
        a2.x = fmaf(wA, vA2.x, fmaf(wB, vB2.x, a2.x));
        a2.y = fmaf(wA, vA2.y, fmaf(wB, vB2.y, a2.y));
        a2.z = fmaf(wA, vA2.z, fmaf(wB, vB2.z, a2.z));
        a2.w = fmaf(wA, vA2.w, fmaf(wB, vB2.w, a2.w));
    }
    for (; e < end; e++) {
        int s = __ldg(&ci[e]);
        float w0 = __ldg(&wv[e]);
        size_t o = (size_t)s * 128 + lane * 4;
        float4 v0 = *(const float4*)&x0[o];
        float4 v1 = *(const float4*)&x1[o];
        float4 v2 = *(const float4*)&x2[o];
        a0.x = fmaf(w0, v0.x, a0.x); a0.y = fmaf(w0, v0.y, a0.y);
        a0.z = fmaf(w0, v0.z, a0.z); a0.w = fmaf(w0, v0.w, a0.w);
        a1.x = fmaf(w0, v1.x, a1.x); a1.y = fmaf(w0, v1.y, a1.y);
        a1.z = fmaf(w0, v1.z, a1.z); a1.w = fmaf(w0, v1.w, a1.w);
        a2.x = fmaf(w0, v2.x, a2.x); a2.y = fmaf(w0, v2.y, a2.y);
        a2.z = fmaf(w0, v2.z, a2.z); a2.w = fmaf(w0, v2.w, a2.w);
    }
    size_t od = (size_t)n * 128 + lane * 4;
    *(float4*)&o0[od] = a0;
    *(float4*)&o1[od] = a1;
    *(float4*)&o2[od] = a2;
}

// ---------------------------------------------------------------------------
// Final epilogue
// ---------------------------------------------------------------------------
__global__ __launch_bounds__(128) void finalize_kernel(
    const float* __restrict__ r0, const float* __restrict__ rA,
    const float* __restrict__ rw, const float* __restrict__ r0s,
    const float* __restrict__ rB, float* __restrict__ out)
{
    const int n = blockIdx.x;
    const int t = threadIdx.x;
    const int lane = t & 31, wid = t >> 5;

    const size_t base = (size_t)n * 128 + t;
    float v0  = r0 [base];
    float vA  = rA [base];
    float vW  = rw [base];
    float v0s = r0s[base];
    float vB  = rB [base];

    float4 sq = make_float4(v0 * v0, vA * vA + vW * vW,
                            v0s * v0s, vB * vB + vW * vW);
#pragma unroll
    for (int o = 16; o; o >>= 1) {
        sq.x += __shfl_xor_sync(0xffffffffu, sq.x, o);
        sq.y += __shfl_xor_sync(0xffffffffu, sq.y, o);
        sq.z += __shfl_xor_sync(0xffffffffu, sq.z, o);
        sq.w += __shfl_xor_sync(0xffffffffu, sq.w, o);
    }
    __shared__ float4 wsum[4];
    if (lane == 0) wsum[wid] = sq;
    __syncthreads();
    float s0  = wsum[0].x + wsum[1].x + wsum[2].x + wsum[3].x;
    float s1  = wsum[0].y + wsum[1].y + wsum[2].y + wsum[3].y;
    float s0s = wsum[0].z + wsum[1].z + wsum[2].z + wsum[3].z;
    float s1s = wsum[0].w + wsum[1].w + wsum[2].w + wsum[3].w;

    const float EPS = 1e-9f;
    float i0  = 1.f / (sqrtf(s0)  + EPS);
    float i1  = 1.f / (sqrtf(s1)  + EPS);
    float i0s = 1.f / (sqrtf(s0s) + EPS);
    float i1s = 1.f / (sqrtf(s1s) + EPS);

    size_t drow = (size_t)n * 384;
    out[drow + t]       = v0 * i0;
    out[drow + 128 + t] = vA * i1;
    out[drow + 256 + t] = vW * i1;

    size_t srow = (size_t)N0_DOCS * 384 + drow;
    out[srow + t]       = v0s * i0s;
    out[srow + 128 + t] = vB * i1s;
    out[srow + 256 + t] = vW * i1s;
}

// ---------------------------------------------------------------------------
// Launch
// ---------------------------------------------------------------------------
extern "C" void kernel_launch(void* const* d_in, const int* in_sizes, int n_in,
                              void* d_out, int out_size)
{
    const float* x1       = (const float*)d_in[0];
    const float* x2       = (const float*)d_in[1];
    const float* word_emb = (const float*)d_in[2];
    const float* W1a = (const float*)d_in[3];
    const float* b1a = (const float*)d_in[4];
    const float* W1b = (const float*)d_in[5];
    const float* b1b = (const float*)d_in[6];
    const float* W2a = (const float*)d_in[7];
    const float* b2a = (const float*)d_in[8];
    const float* W2b = (const float*)d_in[9];
    const float* b2b = (const float*)d_in[10];
    const int*   e11_src = (const int*)d_in[11];
    const int*   e11_dst = (const int*)d_in[12];
    const float* e11_w   = (const float*)d_in[13];
    const int*   e22_src = (const int*)d_in[14];
    const int*   e22_dst = (const int*)d_in[15];
    const float* e22_w   = (const float*)d_in[16];
    const int*   e01_src = (const int*)d_in[17];
    const int*   e01_dst = (const int*)d_in[18];
    const float* e01_w   = (const float*)d_in[19];
    const int*   e02_src = (const int*)d_in[20];
    const int*   e02_dst = (const int*)d_in[21];
    const float* e02_w   = (const float*)d_in[22];

    const int N1  = in_sizes[0] / 256;
    const int N2  = in_sizes[1] / 256;
    const int E11 = in_sizes[11];
    const int E22 = in_sizes[14];
    const int E01 = in_sizes[17];
    const int E02 = in_sizes[20];
    const int Etot = E11 + E22 + E01 + E02;
    const int Ntot = N1 + N2 + 2 * N0_DOCS;
    const int b22 = N1, b01 = N1 + N2, b02 = N1 + N2 + N0_DOCS;

    float *l1_1, *h1, *l2_1, *l1_2, *h2, *l2_2, *r0, *r0s, *rA, *rB, *rw;
    cudaGetSymbolAddress((void**)&l1_1, g_l1_1);
    cudaGetSymbolAddress((void**)&h1,   g_h1);
    cudaGetSymbolAddress((void**)&l2_1, g_l2_1);
    cudaGetSymbolAddress((void**)&l1_2, g_l1_2);
    cudaGetSymbolAddress((void**)&h2,   g_h2);
    cudaGetSymbolAddress((void**)&l2_2, g_l2_2);
    cudaGetSymbolAddress((void**)&r0,   g_r0);
    cudaGetSymbolAddress((void**)&r0s,  g_r0s);
    cudaGetSymbolAddress((void**)&rA,   g_rA);
    cudaGetSymbolAddress((void**)&rB,   g_rB);
    cudaGetSymbolAddress((void**)&rw,   g_rw);

    int *cntfc, *ptr, *ci, *bsum;
    float *wv;
    cudaGetSymbolAddress((void**)&cntfc, g_cntfc);
    cudaGetSymbolAddress((void**)&ptr,   g_ptr);
    cudaGetSymbolAddress((void**)&ci,    g_ci);
    cudaGetSymbolAddress((void**)&wv,    g_wv);
    cudaGetSymbolAddress((void**)&bsum,  g_bsum);
    int* cnt = cntfc;
    int* fc  = cntfc + NTOT;

    static cudaStream_t s1 = nullptr, s2 = nullptr, s3 = nullptr;
    static cudaEvent_t ev0 = nullptr, ev1 = nullptr, ev2 = nullptr, ecsr = nullptr;
    if (s1 == nullptr) {
        cudaStreamCreateWithFlags(&s1, cudaStreamNonBlocking);
        cudaStreamCreateWithFlags(&s2, cudaStreamNonBlocking);
        cudaStreamCreateWithFlags(&s3, cudaStreamNonBlocking);
        cudaEventCreateWithFlags(&ev0, cudaEventDisableTiming);
        cudaEventCreateWithFlags(&ev1, cudaEventDisableTiming);
        cudaEventCreateWithFlags(&ev2, cudaEventDisableTiming);
        cudaEventCreateWithFlags(&ecsr, cudaEventDisableTiming);
    }

    // Fork
    cudaEventRecord(ev0, 0);
    cudaStreamWaitEvent(s1, ev0, 0);
    cudaStreamWaitEvent(s2, ev0, 0);
    cudaStreamWaitEvent(s3, ev0, 0);

    // ---- stream 3: fused CSR build for all 4 graphs ----
    cudaMemsetAsync(cntfc, 0, 2 * NTOT * sizeof(int), s3);
    hist_all_kernel<<<(Etot + 255) / 256, 256, 0, s3>>>(
        e11_dst, e22_dst, e01_dst, e02_dst, E11, E22, E01, E02,
        b22, b01, b02, cnt);
    int nb = (Ntot + SCB - 1) / SCB;
    scan1_kernel<<<nb, SCB, 0, s3>>>(cnt, ptr, bsum, Ntot);
    scan2_kernel<<<1, SCB, 0, s3>>>(bsum, nb);
    scan3_kernel<<<nb, SCB, 0, s3>>>(ptr, bsum, Ntot);
    fill_all_kernel<<<(Etot + 255) / 256, 256, 0, s3>>>(
        e11_src, e11_dst, e11_w, e22_src, e22_dst, e22_w,
        e01_src, e01_dst, e01_w, e02_src, e02_dst, e02_w,
        E11, E22, E01, E02, b22, b01, b02, ptr, fc, ci, wv);
    cudaEventRecord(ecsr, s3);

    // ---- stream 1: type-1 pipeline ----
    gemm128_relu_kernel<<<(N1 + TM - 1) / TM, 256, 0, s1>>>(x1, W1a, b1a, l1_1, N1, 256);
    cudaStreamWaitEvent(s1, ecsr, 0);
    gather1_kernel<<<(N1 * 32 + 255) / 256, 256, 0, s1>>>(
        ptr, cnt, ci, wv, l1_1, h1, N1);
    gemm128_relu_kernel<<<(N1 + TM - 1) / TM, 256, 0, s1>>>(h1, W1b, b1b, l2_1, N1, 128);
    gather2_kernel<<<(N0_DOCS * 32 + 255) / 256, 256, 0, s1>>>(
        ptr + b01, cnt + b01, ci, wv, l2_1, l1_1, r0, r0s, N0_DOCS);
    cudaEventRecord(ev1, s1);

    // ---- stream 2: type-2 pipeline ----
    gemm128_relu_kernel<<<(N2 + TM - 1) / TM, 256, 0, s2>>>(x2, W2a, b2a, l1_2, N2, 256);
    cudaStreamWaitEvent(s2, ecsr, 0);
    gather1_kernel<<<(N2 * 32 + 255) / 256, 256, 0, s2>>>(
        ptr + b22, cnt + b22, ci, wv, l1_2, h2, N2);
    gemm128_relu_kernel<<<(N2 + TM - 1) / TM, 256, 0, s2>>>(h2, W2b, b2b, l2_2, N2, 128);
    gather3_kernel<<<(N0_DOCS * 32 + 255) / 256, 256, 0, s2>>>(
        ptr + b02, cnt + b02, ci, wv, l2_2, l1_2, word_emb, rA, rB, rw, N0_DOCS);
    cudaEventRecord(ev2, s2);

    // ---- join + finalize ----
    cudaStreamWaitEvent(0, ev1, 0);
    cudaStreamWaitEvent(0, ev2, 0);
    finalize_kernel<<<N0_DOCS, 128, 0, 0>>>(r0, rA, rw, r0s, rB, (float*)d_out);
}

// round 6
// speedup vs baseline: 2.3086x; 1.2480x over previous
#include <cuda_runtime.h>
#include <cuda_bf16.h>
#include <math.h>

typedef unsigned long long ull;
typedef unsigned int u32;

#define N0_DOCS 10000
#define MAXN1 50000
#define MAXN2 30000
#define NTOT (MAXN1 + MAXN2 + 2 * N0_DOCS)
#define ETOT (800000 + 480000 + 320000 + 160000)

// ---------------- feature scratch ----------------
__device__ float g_l1_1[MAXN1 * 128];
__device__ float g_h1  [MAXN1 * 128];
__device__ float g_l2_1[MAXN1 * 128];
__device__ float g_l1_2[MAXN2 * 128];
__device__ float g_h2  [MAXN2 * 128];
__device__ float g_l2_2[MAXN2 * 128];
__device__ float g_r0 [N0_DOCS * 128];
__device__ float g_r0s[N0_DOCS * 128];
__device__ float g_rA [N0_DOCS * 128];
__device__ float g_rB [N0_DOCS * 128];
__device__ float g_rw [N0_DOCS * 128];

// ---------------- CSR scratch ----------------
__device__ int   g_cntfc[2 * NTOT];
__device__ int   g_ptr[NTOT];
__device__ int   g_ci[ETOT];
__device__ float g_wv[ETOT];
__device__ int   g_bsum[128];

// ---------------------------------------------------------------------------
// helpers
// ---------------------------------------------------------------------------
__device__ __forceinline__ u32 smem_u32(const void* p) {
    u32 a;
    asm("{ .reg .u64 t; cvta.to.shared.u64 t, %1; cvt.u32.u64 %0, t; }"
        : "=r"(a) : "l"(p));
    return a;
}
// pack two floats as bf16x2 (lo half = a, hi half = b)
__device__ __forceinline__ u32 pack_bf2(float a, float b) {
    u32 r;
    asm("cvt.rn.bf16x2.f32 %0, %1, %2;" : "=r"(r) : "f"(b), "f"(a));
    return r;
}
__device__ __forceinline__ float bf_to_f(u32 lo16) {
    return __uint_as_float(lo16 << 16);
}

#define LDM4(r, addr)                                                          \
    asm volatile("ldmatrix.sync.aligned.m8n8.x4.shared.b16 {%0,%1,%2,%3}, [%4];" \
                 : "=r"((r)[0]), "=r"((r)[1]), "=r"((r)[2]), "=r"((r)[3])      \
                 : "r"(addr))

#define MMA16816(c, a, b0v, b1v)                                               \
    asm volatile("mma.sync.aligned.m16n8k16.row.col.f32.bf16.bf16.f32 "        \
                 "{%0,%1,%2,%3}, {%4,%5,%6,%7}, {%8,%9}, {%0,%1,%2,%3};"       \
                 : "+f"((c)[0]), "+f"((c)[1]), "+f"((c)[2]), "+f"((c)[3])      \
                 : "r"((a)[0]), "r"((a)[1]), "r"((a)[2]), "r"((a)[3]),         \
                   "r"(b0v), "r"(b1v))

// ===========================================================================
// Tensor-core (mma.sync bf16, hi/lo split) GEMM + bias + ReLU
//   C[M,128] = relu(A[M,K] @ W[K,128] + b)
// CTA tile 128x128, 8 warps (4m x 2n), warp tile 32x64, K-step 32.
// SMEM rows padded to 80B for conflict-free ldmatrix.
// ===========================================================================
__global__ __launch_bounds__(256) void gemm_mma_kernel(
    const float* __restrict__ A, const float* __restrict__ W,
    const float* __restrict__ bias, float* __restrict__ C,
    int M, int K)
{
    __shared__ __align__(16) unsigned char smbuf[4 * 10240];
    const u32 sb  = smem_u32(smbuf);
    const u32 AHI = sb, ALO = sb + 10240, BHI = sb + 20480, BLO = sb + 30720;

    const int tid  = threadIdx.x;
    const int lane = tid & 31, wid = tid >> 5;
    const int wm = wid & 3, wn = wid >> 2;          // warp grid 4m x 2n
    const int lr = lane & 7, sub = lane >> 3;
    const int row0 = blockIdx.x * 128;

    const int arow = tid >> 1, akh = (tid & 1) * 16;      // A staging
    const int bn   = tid & 127, bkh = (tid >> 7) * 16;    // B staging

    float acc[2][8][4];
#pragma unroll
    for (int i = 0; i < 2; i++)
#pragma unroll
        for (int j = 0; j < 8; j++)
#pragma unroll
            for (int c = 0; c < 4; c++) acc[i][j][c] = 0.f;

    // precomputed ldmatrix smem offsets (byte), j-chunk adds 32
    const u32 a_off = (u32)((wm * 32 + lr + (sub & 1) * 8) * 80 + (sub >> 1) * 16);
    const u32 b_off = (u32)((wn * 64 + lr + (sub >> 1) * 8) * 80 + (sub & 1) * 16);

    for (int k0 = 0; k0 < K; k0 += 32) {
        __syncthreads();
        // ---- stage A (128 rows x 32 k), hi/lo split ----
        {
            const int gr = row0 + arow;
            const float* ap = A + (size_t)gr * K + k0 + akh;
            const u32 dh = AHI + arow * 80 + akh * 2;
            const u32 dl = ALO + arow * 80 + akh * 2;
#pragma unroll
            for (int q = 0; q < 4; q++) {
                float4 v = make_float4(0.f, 0.f, 0.f, 0.f);
                if (gr < M) v = *(const float4*)(ap + q * 4);
                u32 h0 = pack_bf2(v.x, v.y);
                u32 h1 = pack_bf2(v.z, v.w);
                float lx = v.x - bf_to_f(h0 & 0xFFFFu);
                float ly = v.y - bf_to_f(h0 >> 16);
                float lz = v.z - bf_to_f(h1 & 0xFFFFu);
                float lw = v.w - bf_to_f(h1 >> 16);
                u32 l0 = pack_bf2(lx, ly);
                u32 l1 = pack_bf2(lz, lw);
                asm volatile("st.shared.v2.b32 [%0], {%1,%2};"
                             :: "r"(dh + q * 8), "r"(h0), "r"(h1));
                asm volatile("st.shared.v2.b32 [%0], {%1,%2};"
                             :: "r"(dl + q * 8), "r"(l0), "r"(l1));
            }
        }
        // ---- stage B^T (128 n rows x 32 k), hi/lo split ----
        {
            const float* wp = W + (size_t)(k0 + bkh) * 128 + bn;
            const u32 dh = BHI + bn * 80 + bkh * 2;
            const u32 dl = BLO + bn * 80 + bkh * 2;
#pragma unroll
            for (int q = 0; q < 4; q++) {
                float w0 = __ldg(wp + (4 * q + 0) * 128);
                float w1 = __ldg(wp + (4 * q + 1) * 128);
                float w2 = __ldg(wp + (4 * q + 2) * 128);
                float w3 = __ldg(wp + (4 * q + 3) * 128);
                u32 h0 = pack_bf2(w0, w1);
                u32 h1 = pack_bf2(w2, w3);
                float l0f = w0 - bf_to_f(h0 & 0xFFFFu);
                float l1f = w1 - bf_to_f(h0 >> 16);
                float l2f = w2 - bf_to_f(h1 & 0xFFFFu);
                float l3f = w3 - bf_to_f(h1 >> 16);
                u32 l0 = pack_bf2(l0f, l1f);
                u32 l1 = pack_bf2(l2f, l3f);
                asm volatile("st.shared.v2.b32 [%0], {%1,%2};"
                             :: "r"(dh + q * 8), "r"(h0), "r"(h1));
                asm volatile("st.shared.v2.b32 [%0], {%1,%2};"
                             :: "r"(dl + q * 8), "r"(l0), "r"(l1));
            }
        }
        __syncthreads();

        // ---- MMA over the 2 k16 chunks ----
#pragma unroll
        for (int j = 0; j < 2; j++) {
            u32 ah[2][4], al[2][4];
#pragma unroll
            for (int i = 0; i < 2; i++) {
                const u32 ro = a_off + i * 16 * 80 + j * 32;
                LDM4(ah[i], AHI + ro);
                LDM4(al[i], ALO + ro);
            }
#pragma unroll
            for (int p = 0; p < 4; p++) {
                const u32 bo = b_off + p * 16 * 80 + j * 32;
                u32 bh[4], bl[4];
                LDM4(bh, BHI + bo);
                LDM4(bl, BLO + bo);
#pragma unroll
                for (int i = 0; i < 2; i++) {
                    MMA16816(acc[i][2 * p],     ah[i], bh[0], bh[1]);
                    MMA16816(acc[i][2 * p],     ah[i], bl[0], bl[1]);
                    MMA16816(acc[i][2 * p],     al[i], bh[0], bh[1]);
                    MMA16816(acc[i][2 * p + 1], ah[i], bh[2], bh[3]);
                    MMA16816(acc[i][2 * p + 1], ah[i], bl[2], bl[3]);
                    MMA16816(acc[i][2 * p + 1], al[i], bh[2], bh[3]);
                }
            }
        }
    }

    // ---- epilogue: bias + relu, write C ----
    const int gid = lane >> 2, tig = lane & 3;
#pragma unroll
    for (int i = 0; i < 2; i++) {
        const int ra = row0 + wm * 32 + i * 16 + gid;
        const int rb = ra + 8;
#pragma unroll
        for (int j8 = 0; j8 < 8; j8++) {
            const int col = wn * 64 + j8 * 8 + tig * 2;
            float b0 = __ldg(&bias[col]);
            float b1 = __ldg(&bias[col + 1]);
            if (ra < M) {
                float2 o;
                o.x = fmaxf(acc[i][j8][0] + b0, 0.f);
                o.y = fmaxf(acc[i][j8][1] + b1, 0.f);
                *(float2*)&C[(size_t)ra * 128 + col] = o;
            }
            if (rb < M) {
                float2 o;
                o.x = fmaxf(acc[i][j8][2] + b0, 0.f);
                o.y = fmaxf(acc[i][j8][3] + b1, 0.f);
                *(float2*)&C[(size_t)rb * 128 + col] = o;
            }
        }
    }
}

// ===========================================================================
// Fused CSR build (unchanged)
// ===========================================================================
__global__ __launch_bounds__(256) void hist_all_kernel(
    const int* __restrict__ d11, const int* __restrict__ d22,
    const int* __restrict__ d01, const int* __restrict__ d02,
    int E11, int E22, int E01, int E02,
    int b22, int b01, int b02,
    int* __restrict__ cnt)
{
    int i = blockIdx.x * blockDim.x + threadIdx.x;
    int E12 = E11 + E22, E123 = E12 + E01, E = E123 + E02;
    if (i >= E) return;
    int node;
    if (i < E11)       node =        d11[i];
    else if (i < E12)  node = b22 +  d22[i - E11];
    else if (i < E123) node = b01 +  d01[i - E12];
    else               node = b02 +  d02[i - E123];
    atomicAdd(&cnt[node], 1);
}

#define SCB 1024
__global__ __launch_bounds__(SCB) void scan1_kernel(
    const int* __restrict__ in, int* __restrict__ out, int* __restrict__ bsum, int n)
{
    __shared__ int sh[SCB];
    int i = blockIdx.x * SCB + threadIdx.x;
    int v = (i < n) ? in[i] : 0;
    sh[threadIdx.x] = v;
    __syncthreads();
#pragma unroll
    for (int o = 1; o < SCB; o <<= 1) {
        int t = (threadIdx.x >= o) ? sh[threadIdx.x - o] : 0;
        __syncthreads();
        sh[threadIdx.x] += t;
        __syncthreads();
    }
    if (i < n) out[i] = sh[threadIdx.x] - v;
    if (threadIdx.x == SCB - 1) bsum[blockIdx.x] = sh[threadIdx.x];
}

__global__ __launch_bounds__(SCB) void scan2_kernel(int* __restrict__ bsum, int nb)
{
    __shared__ int sh[SCB];
    int v = (threadIdx.x < nb) ? bsum[threadIdx.x] : 0;
    sh[threadIdx.x] = v;
    __syncthreads();
#pragma unroll
    for (int o = 1; o < SCB; o <<= 1) {
        int t = (threadIdx.x >= o) ? sh[threadIdx.x - o] : 0;
        __syncthreads();
        sh[threadIdx.x] += t;
        __syncthreads();
    }
    if (threadIdx.x < nb) bsum[threadIdx.x] = sh[threadIdx.x] - v;
}

__global__ __launch_bounds__(SCB) void scan3_kernel(
    int* __restrict__ out, const int* __restrict__ bsum, int n)
{
    int i = blockIdx.x * SCB + threadIdx.x;
    if (i < n) out[i] += bsum[blockIdx.x];
}

__global__ __launch_bounds__(256) void fill_all_kernel(
    const int* __restrict__ s11, const int* __restrict__ d11, const float* __restrict__ w11,
    const int* __restrict__ s22, const int* __restrict__ d22, const float* __restrict__ w22,
    const int* __restrict__ s01, const int* __restrict__ d01, const float* __restrict__ w01,
    const int* __restrict__ s02, const int* __restrict__ d02, const float* __restrict__ w02,
    int E11, int E22, int E01, int E02,
    int b22, int b01, int b02,
    const int* __restrict__ ptr, int* __restrict__ fc,
    int* __restrict__ ci, float* __restrict__ wv)
{
    int i = blockIdx.x * blockDim.x + threadIdx.x;
    int E12 = E11 + E22, E123 = E12 + E01, E = E123 + E02;
    if (i >= E) return;
    int node, s; float w;
    if (i < E11)       { node =       d11[i];        s = s11[i];        w = w11[i]; }
    else if (i < E12)  { int j = i - E11;  node = b22 + d22[j]; s = s22[j]; w = w22[j]; }
    else if (i < E123) { int j = i - E12;  node = b01 + d01[j]; s = s01[j]; w = w01[j]; }
    else               { int j = i - E123; node = b02 + d02[j]; s = s02[j]; w = w02[j]; }
    int pos = ptr[node] + atomicAdd(&fc[node], 1);
    ci[pos] = s;
    wv[pos] = w;
}

// ===========================================================================
// Gather SpMM kernels (unchanged)
// ===========================================================================
__global__ __launch_bounds__(256) void gather1_kernel(
    const int* __restrict__ ptr, const int* __restrict__ cnt,
    const int* __restrict__ ci, const float* __restrict__ wv,
    const float* __restrict__ x, float* __restrict__ out, int N)
{
    int t = blockIdx.x * blockDim.x + threadIdx.x;
    int n = t >> 5;
    if (n >= N) return;
    int lane = t & 31;

    int beg = __ldg(&ptr[n]);
    int end = beg + __ldg(&cnt[n]);
    float4 acc = make_float4(0.f, 0.f, 0.f, 0.f);

    int e = beg;
    for (; e + 4 <= end; e += 4) {
        int s0 = __ldg(&ci[e]),   s1 = __ldg(&ci[e+1]);
        int s2 = __ldg(&ci[e+2]), s3 = __ldg(&ci[e+3]);
        float w0 = __ldg(&wv[e]),   w1 = __ldg(&wv[e+1]);
        float w2 = __ldg(&wv[e+2]), w3 = __ldg(&wv[e+3]);
        float4 v0 = *(const float4*)&x[(size_t)s0 * 128 + lane * 4];
        float4 v1 = *(const float4*)&x[(size_t)s1 * 128 + lane * 4];
        float4 v2 = *(const float4*)&x[(size_t)s2 * 128 + lane * 4];
        float4 v3 = *(const float4*)&x[(size_t)s3 * 128 + lane * 4];
        acc.x = fmaf(w0, v0.x, fmaf(w1, v1.x, fmaf(w2, v2.x, fmaf(w3, v3.x, acc.x))));
        acc.y = fmaf(w0, v0.y, fmaf(w1, v1.y, fmaf(w2, v2.y, fmaf(w3, v3.y, acc.y))));
        acc.z = fmaf(w0, v0.z, fmaf(w1, v1.z, fmaf(w2, v2.z, fmaf(w3, v3.z, acc.z))));
        acc.w = fmaf(w0, v0.w, fmaf(w1, v1.w, fmaf(w2, v2.w, fmaf(w3, v3.w, acc.w))));
    }
    for (; e < end; e++) {
        int s = __ldg(&ci[e]);
        float w0 = __ldg(&wv[e]);
        float4 v = *(const float4*)&x[(size_t)s * 128 + lane * 4];
        acc.x = fmaf(w0, v.x, acc.x);
        acc.y = fmaf(w0, v.y, acc.y);
        acc.z = fmaf(w0, v.z, acc.z);
        acc.w = fmaf(w0, v.w, acc.w);
    }
    *(float4*)&out[(size_t)n * 128 + lane * 4] = acc;
}

__global__ __launch_bounds__(256) void gather2_kernel(
    const int* __restrict__ ptr, const int* __restrict__ cnt,
    const int* __restrict__ ci, const float* __restrict__ wv,
    const float* __restrict__ x0, const float* __restrict__ x1,
    float* __restrict__ o0, float* __restrict__ o1, int N)
{
    int t = blockIdx.x * blockDim.x + threadIdx.x;
    int n = t >> 5;
    if (n >= N) return;
    int lane = t & 31;

    int beg = __ldg(&ptr[n]);
    int end = beg + __ldg(&cnt[n]);
    float4 a0 = make_float4(0.f, 0.f, 0.f, 0.f);
    float4 a1 = a0;

    int e = beg;
    for (; e + 2 <= end; e += 2) {
        int sA = __ldg(&ci[e]), sB = __ldg(&ci[e+1]);
        float wA = __ldg(&wv[e]), wB = __ldg(&wv[e+1]);
        size_t oA = (size_t)sA * 128 + lane * 4;
        size_t oB = (size_t)sB * 128 + lane * 4;
        float4 vA0 = *(const float4*)&x0[oA];
        float4 vB0 = *(const float4*)&x0[oB];
        float4 vA1 = *(const float4*)&x1[oA];
        float4 vB1 = *(const float4*)&x1[oB];
        a0.x = fmaf(wA, vA0.x, fmaf(wB, vB0.x, a0.x));
        a0.y = fmaf(wA, vA0.y, fmaf(wB, vB0.y, a0.y));
        a0.z = fmaf(wA, vA0.z, fmaf(wB, vB0.z, a0.z));
        a0.w = fmaf(wA, vA0.w, fmaf(wB, vB0.w, a0.w));
        a1.x = fmaf(wA, vA1.x, fmaf(wB, vB1.x, a1.x));
        a1.y = fmaf(wA, vA1.y, fmaf(wB, vB1.y, a1.y));
        a1.z = fmaf(wA, vA1.z, fmaf(wB, vB1.z, a1.z));
        a1.w = fmaf(wA, vA1.w, fmaf(wB, vB1.w, a1.w));
    }
    for (; e < end; e++) {
        int s = __ldg(&ci[e]);
        float w0 = __ldg(&wv[e]);
        size_t o = (size_t)s * 128 + lane * 4;
        float4 v0 = *(const float4*)&x0[o];
        float4 v1 = *(const float4*)&x1[o];
        a0.x = fmaf(w0, v0.x, a0.x); a0.y = fmaf(w0, v0.y, a0.y);
        a0.z = fmaf(w0, v0.z, a0.z); a0.w = fmaf(w0, v0.w, a0.w);
        a1.x = fmaf(w0, v1.x, a1.x); a1.y = fmaf(w0, v1.y, a1.y);
        a1.z = fmaf(w0, v1.z, a1.z); a1.w = fmaf(w0, v1.w, a1.w);
    }
    size_t od = (size_t)n * 128 + lane * 4;
    *(float4*)&o0[od] = a0;
    *(float4*)&o1[od] = a1;
}

__global__ __launch_bounds__(256) void gather3_kernel(
    const int* __restrict__ ptr, const int* __restrict__ cnt,
    const int* __restrict__ ci, const float* __restrict__ wv,
    const float* __restrict__ x0, const float* __restrict__ x1,
    const float* __restrict__ x2,
    float* __restrict__ o0, float* __restrict__ o1, float* __restrict__ o2, int N)
{
    int t = blockIdx.x * blockDim.x + threadIdx.x;
    int n = t >> 5;
    if (n >= N) return;
    int lane = t & 31;

    int beg = __ldg(&ptr[n]);
    int end = beg + __ldg(&cnt[n]);
    float4 a0 = make_float4(0.f, 0.f, 0.f, 0.f);
    float4 a1 = a0, a2 = a0;

    int e = beg;
    for (; e + 2 <= end; e += 2) {
        int sA = __ldg(&ci[e]), sB = __ldg(&ci[e+1]);
        float wA = __ldg(&wv[e]), wB = __ldg(&wv[e+1]);
        size_t oA = (size_t)sA * 128 + lane * 4;
        size_t oB = (size_t)sB * 128 + lane * 4;
        float4 vA0 = *(const float4*)&x0[oA];
        float4 vB0 = *(const float4*)&x0[oB];
        float4 vA1 = *(const float4*)&x1[oA];
        float4 vB1 = *(const float4*)&x1[oB];
        float4 vA2 = *(const float4*)&x2[oA];
        float4 vB2 = *(const float4*)&x2[oB];
        a0.x = fmaf(wA, vA0.x, fmaf(wB, vB0.x, a0.x));
        a0.y = fmaf(wA, vA0.y, fmaf(wB, vB0.y, a0.y));
        a0.z = fmaf(wA, vA0.z, fmaf(wB, vB0.z, a0.z));
        a0.w = fmaf(wA, vA0.w, fmaf(wB, vB0.w, a0.w));
        a1.x = fmaf(wA, vA1.x, fmaf(wB, vB1.x, a1.x));
        a1.y = fmaf(wA, vA1.y, fmaf(wB, vB1.y, a1.y));
        a1.z = fmaf(wA, vA1.z, fmaf(wB, vB1.z, a1.z));
        a1.w = fmaf(wA, vA1.w, fmaf(wB, vB1.w, a1.w));
        a2.x = fmaf(wA, vA2.x, fmaf(wB, vB2.x, a2.x));
        a2.y = fmaf(wA, vA2.y, fmaf(wB, vB2.y, a2.y));
        a2.z = fmaf(wA, vA2.z, fmaf(wB, vB2.z, a2.z));
        a2.w = fmaf(wA, vA2.w, fmaf(wB, vB2.w, a2.w));
    }
    for (; e < end; e++) {
        int s = __ldg(&ci[e]);
        float w0 = __ldg(&wv[e]);
        size_t o = (size_t)s * 128 + lane * 4;
        float4 v0 = *(const float4*)&x0[o];
        float4 v1 = *(const float4*)&x1[o];
        float4 v2 = *(const float4*)&x2[o];
        a0.x = fmaf(w0, v0.x, a0.x); a0.y = fmaf(w0, v0.y, a0.y);
        a0.z = fmaf(w0, v0.z, a0.z); a0.w = fmaf(w0, v0.w, a0.w);
        a1.x = fmaf(w0, v1.x, a1.x); a1.y = fmaf(w0, v1.y, a1.y);
        a1.z = fmaf(w0, v1.z, a1.z); a1.w = fmaf(w0, v1.w, a1.w);
        a2.x = fmaf(w0, v2.x, a2.x); a2.y = fmaf(w0, v2.y, a2.y);
        a2.z = fmaf(w0, v2.z, a2.z); a2.w = fmaf(w0, v2.w, a2.w);
    }
    size_t od = (size_t)n * 128 + lane * 4;
    *(float4*)&o0[od] = a0;
    *(float4*)&o1[od] = a1;
    *(float4*)&o2[od] = a2;
}

// ===========================================================================
// Final epilogue (unchanged)
// ===========================================================================
__global__ __launch_bounds__(128) void finalize_kernel(
    const float* __restrict__ r0, const float* __restrict__ rA,
    const float* __restrict__ rw, const float* __restrict__ r0s,
    const float* __restrict__ rB, float* __restrict__ out)
{
    const int n = blockIdx.x;
    const int t = threadIdx.x;
    const int lane = t & 31, wid = t >> 5;

    const size_t base = (size_t)n * 128 + t;
    float v0  = r0 [base];
    float vA  = rA [base];
    float vW  = rw [base];
    float v0s = r0s[base];
    float vB  = rB [base];

    float4 sq = make_float4(v0 * v0, vA * vA + vW * vW,
                            v0s * v0s, vB * vB + vW * vW);
#pragma unroll
    for (int o = 16; o; o >>= 1) {
        sq.x += __shfl_xor_sync(0xffffffffu, sq.x, o);
        sq.y += __shfl_xor_sync(0xffffffffu, sq.y, o);
        sq.z += __shfl_xor_sync(0xffffffffu, sq.z, o);
        sq.w += __shfl_xor_sync(0xffffffffu, sq.w, o);
    }
    __shared__ float4 wsum[4];
    if (lane == 0) wsum[wid] = sq;
    __syncthreads();
    float s0  = wsum[0].x + wsum[1].x + wsum[2].x + wsum[3].x;
    float s1  = wsum[0].y + wsum[1].y + wsum[2].y + wsum[3].y;
    float s0s = wsum[0].z + wsum[1].z + wsum[2].z + wsum[3].z;
    float s1s = wsum[0].w + wsum[1].w + wsum[2].w + wsum[3].w;

    const float EPS = 1e-9f;
    float i0  = 1.f / (sqrtf(s0)  + EPS);
    float i1  = 1.f / (sqrtf(s1)  + EPS);
    float i0s = 1.f / (sqrtf(s0s) + EPS);
    float i1s = 1.f / (sqrtf(s1s) + EPS);

    size_t drow = (size_t)n * 384;
    out[drow + t]       = v0 * i0;
    out[drow + 128 + t] = vA * i1;
    out[drow + 256 + t] = vW * i1;

    size_t srow = (size_t)N0_DOCS * 384 + drow;
    out[srow + t]       = v0s * i0s;
    out[srow + 128 + t] = vB * i1s;
    out[srow + 256 + t] = vW * i1s;
}

// ===========================================================================
// Launch
// ===========================================================================
extern "C" void kernel_launch(void* const* d_in, const int* in_sizes, int n_in,
                              void* d_out, int out_size)
{
    const float* x1       = (const float*)d_in[0];
    const float* x2       = (const float*)d_in[1];
    const float* word_emb = (const float*)d_in[2];
    const float* W1a = (const float*)d_in[3];
    const float* b1a = (const float*)d_in[4];
    const float* W1b = (const float*)d_in[5];
    const float* b1b = (const float*)d_in[6];
    const float* W2a = (const float*)d_in[7];
    const float* b2a = (const float*)d_in[8];
    const float* W2b = (const float*)d_in[9];
    const float* b2b = (const float*)d_in[10];
    const int*   e11_src = (const int*)d_in[11];
    const int*   e11_dst = (const int*)d_in[12];
    const float* e11_w   = (const float*)d_in[13];
    const int*   e22_src = (const int*)d_in[14];
    const int*   e22_dst = (const int*)d_in[15];
    const float* e22_w   = (const float*)d_in[16];
    const int*   e01_src = (const int*)d_in[17];
    const int*   e01_dst = (const int*)d_in[18];
    const float* e01_w   = (const float*)d_in[19];
    const int*   e02_src = (const int*)d_in[20];
    const int*   e02_dst = (const int*)d_in[21];
    const float* e02_w   = (const float*)d_in[22];

    const int N1  = in_sizes[0] / 256;
    const int N2  = in_sizes[1] / 256;
    const int E11 = in_sizes[11];
    const int E22 = in_sizes[14];
    const int E01 = in_sizes[17];
    const int E02 = in_sizes[20];
    const int Etot = E11 + E22 + E01 + E02;
    const int Ntot = N1 + N2 + 2 * N0_DOCS;
    const int b22 = N1, b01 = N1 + N2, b02 = N1 + N2 + N0_DOCS;

    float *l1_1, *h1, *l2_1, *l1_2, *h2, *l2_2, *r0, *r0s, *rA, *rB, *rw;
    cudaGetSymbolAddress((void**)&l1_1, g_l1_1);
    cudaGetSymbolAddress((void**)&h1,   g_h1);
    cudaGetSymbolAddress((void**)&l2_1, g_l2_1);
    cudaGetSymbolAddress((void**)&l1_2, g_l1_2);
    cudaGetSymbolAddress((void**)&h2,   g_h2);
    cudaGetSymbolAddress((void**)&l2_2, g_l2_2);
    cudaGetSymbolAddress((void**)&r0,   g_r0);
    cudaGetSymbolAddress((void**)&r0s,  g_r0s);
    cudaGetSymbolAddress((void**)&rA,   g_rA);
    cudaGetSymbolAddress((void**)&rB,   g_rB);
    cudaGetSymbolAddress((void**)&rw,   g_rw);

    int *cntfc, *ptr, *ci, *bsum;
    float *wv;
    cudaGetSymbolAddress((void**)&cntfc, g_cntfc);
    cudaGetSymbolAddress((void**)&ptr,   g_ptr);
    cudaGetSymbolAddress((void**)&ci,    g_ci);
    cudaGetSymbolAddress((void**)&wv,    g_wv);
    cudaGetSymbolAddress((void**)&bsum,  g_bsum);
    int* cnt = cntfc;
    int* fc  = cntfc + NTOT;

    static cudaStream_t s1 = nullptr, s2 = nullptr, s3 = nullptr;
    static cudaEvent_t ev0 = nullptr, ev1 = nullptr, ev2 = nullptr, ecsr = nullptr;
    if (s1 == nullptr) {
        cudaStreamCreateWithFlags(&s1, cudaStreamNonBlocking);
        cudaStreamCreateWithFlags(&s2, cudaStreamNonBlocking);
        cudaStreamCreateWithFlags(&s3, cudaStreamNonBlocking);
        cudaEventCreateWithFlags(&ev0, cudaEventDisableTiming);
        cudaEventCreateWithFlags(&ev1, cudaEventDisableTiming);
        cudaEventCreateWithFlags(&ev2, cudaEventDisableTiming);
        cudaEventCreateWithFlags(&ecsr, cudaEventDisableTiming);
    }

    // Fork
    cudaEventRecord(ev0, 0);
    cudaStreamWaitEvent(s1, ev0, 0);
    cudaStreamWaitEvent(s2, ev0, 0);
    cudaStreamWaitEvent(s3, ev0, 0);

    // ---- stream 3: fused CSR build ----
    cudaMemsetAsync(cntfc, 0, 2 * NTOT * sizeof(int), s3);
    hist_all_kernel<<<(Etot + 255) / 256, 256, 0, s3>>>(
        e11_dst, e22_dst, e01_dst, e02_dst, E11, E22, E01, E02,
        b22, b01, b02, cnt);
    int nb = (Ntot + SCB - 1) / SCB;
    scan1_kernel<<<nb, SCB, 0, s3>>>(cnt, ptr, bsum, Ntot);
    scan2_kernel<<<1, SCB, 0, s3>>>(bsum, nb);
    scan3_kernel<<<nb, SCB, 0, s3>>>(ptr, bsum, Ntot);
    fill_all_kernel<<<(Etot + 255) / 256, 256, 0, s3>>>(
        e11_src, e11_dst, e11_w, e22_src, e22_dst, e22_w,
        e01_src, e01_dst, e01_w, e02_src, e02_dst, e02_w,
        E11, E22, E01, E02, b22, b01, b02, ptr, fc, ci, wv);
    cudaEventRecord(ecsr, s3);

    // ---- stream 1: type-1 pipeline ----
    gemm_mma_kernel<<<(N1 + 127) / 128, 256, 0, s1>>>(x1, W1a, b1a, l1_1, N1, 256);
    cudaStreamWaitEvent(s1, ecsr, 0);
    gather1_kernel<<<(N1 * 32 + 255) / 256, 256, 0, s1>>>(
        ptr, cnt, ci, wv, l1_1, h1, N1);
    gemm_mma_kernel<<<(N1 + 127) / 128, 256, 0, s1>>>(h1, W1b, b1b, l2_1, N1, 128);
    gather2_kernel<<<(N0_DOCS * 32 + 255) / 256, 256, 0, s1>>>(
        ptr + b01, cnt + b01, ci, wv, l2_1, l1_1, r0, r0s, N0_DOCS);
    cudaEventRecord(ev1, s1);

    // ---- stream 2: type-2 pipeline ----
    gemm_mma_kernel<<<(N2 + 127) / 128, 256, 0, s2>>>(x2, W2a, b2a, l1_2, N2, 256);
    cudaStreamWaitEvent(s2, ecsr, 0);
    gather1_kernel<<<(N2 * 32 + 255) / 256, 256, 0, s2>>>(
        ptr + b22, cnt + b22, ci, wv, l1_2, h2, N2);
    gemm_mma_kernel<<<(N2 + 127) / 128, 256, 0, s2>>>(h2, W2b, b2b, l2_2, N2, 128);
    gather3_kernel<<<(N0_DOCS * 32 + 255) / 256, 256, 0, s2>>>(
        ptr + b02, cnt + b02, ci, wv, l2_2, l1_2, word_emb, rA, rB, rw, N0_DOCS);
    cudaEventRecord(ev2, s2);

    // ---- join + finalize ----
    cudaStreamWaitEvent(0, ev1, 0);
    cudaStreamWaitEvent(0, ev2, 0);
    finalize_kernel<<<N0_DOCS, 128, 0, 0>>>(r0, rA, rw, r0s, rB, (float*)d_out);
}

// round 7
// speedup vs baseline: 2.6281x; 1.1384x over previous
#include <cuda_runtime.h>
#include <cuda_bf16.h>
#include <math.h>

typedef unsigned long long ull;
typedef unsigned int u32;

#define N0_DOCS 10000
#define MAXN1 50000
#define MAXN2 30000
#define NTOT (MAXN1 + MAXN2 + 2 * N0_DOCS)
#define ETOT (800000 + 480000 + 320000 + 160000)

// ---------------- feature scratch ----------------
__device__ float g_l1_1[MAXN1 * 128];
__device__ float g_h1  [MAXN1 * 128];
__device__ float g_l2_1[MAXN1 * 128];
__device__ float g_l1_2[MAXN2 * 128];
__device__ float g_h2  [MAXN2 * 128];
__device__ float g_l2_2[MAXN2 * 128];
__device__ float g_r0 [N0_DOCS * 128];
__device__ float g_r0s[N0_DOCS * 128];
__device__ float g_rA [N0_DOCS * 128];
__device__ float g_rB [N0_DOCS * 128];
__device__ float g_rw [N0_DOCS * 128];

// ---------------- CSR scratch ----------------
__device__ int   g_cntfc[2 * NTOT];
__device__ int   g_ptr[NTOT];
__device__ int   g_ci[ETOT];
__device__ float g_wv[ETOT];
__device__ int   g_bsum[128];

// ---------------------------------------------------------------------------
// helpers
// ---------------------------------------------------------------------------
__device__ __forceinline__ u32 smem_u32(const void* p) {
    u32 a;
    asm("{ .reg .u64 t; cvta.to.shared.u64 t, %1; cvt.u32.u64 %0, t; }"
        : "=r"(a) : "l"(p));
    return a;
}
__device__ __forceinline__ u32 pack_bf2(float a, float b) {
    u32 r;
    asm("cvt.rn.bf16x2.f32 %0, %1, %2;" : "=r"(r) : "f"(b), "f"(a));
    return r;
}
__device__ __forceinline__ float bf_to_f(u32 lo16) {
    return __uint_as_float(lo16 << 16);
}

#define LDM4(r, addr)                                                          \
    asm volatile("ldmatrix.sync.aligned.m8n8.x4.shared.b16 {%0,%1,%2,%3}, [%4];" \
                 : "=r"((r)[0]), "=r"((r)[1]), "=r"((r)[2]), "=r"((r)[3])      \
                 : "r"(addr))

#define MMA16816(c, a, b0v, b1v)                                               \
    asm volatile("mma.sync.aligned.m16n8k16.row.col.f32.bf16.bf16.f32 "        \
                 "{%0,%1,%2,%3}, {%4,%5,%6,%7}, {%8,%9}, {%0,%1,%2,%3};"       \
                 : "+f"((c)[0]), "+f"((c)[1]), "+f"((c)[2]), "+f"((c)[3])      \
                 : "r"((a)[0]), "r"((a)[1]), "r"((a)[2]), "r"((a)[3]),         \
                   "r"(b0v), "r"(b1v))

#define GEMM_STAGE 10240
#define GEMM_BUF   (4 * GEMM_STAGE)      // 40960 per buffer (AHI/ALO/BHI/BLO)
#define GEMM_SMEM  (2 * GEMM_BUF)        // 81920 double-buffered

// ===========================================================================
// Tensor-core (mma.sync bf16, hi/lo split) GEMM + bias + ReLU, pipelined.
//   C[M,128] = relu(A[M,K] @ W[K,128] + b)
// CTA tile 128x128, 8 warps (4m x 2n), K-step 32, double-buffered SMEM,
// register prefetch of the next K-slice overlapped with MMA.
// ===========================================================================
__global__ __launch_bounds__(256) void gemm_mma_kernel(
    const float* __restrict__ A, const float* __restrict__ W,
    const float* __restrict__ bias, float* __restrict__ C,
    int M, int K)
{
    extern __shared__ __align__(16) unsigned char smbuf[];
    const u32 sb = smem_u32(smbuf);

    const int tid  = threadIdx.x;
    const int lane = tid & 31, wid = tid >> 5;
    const int wm = wid & 3, wn = wid >> 2;
    const int lr = lane & 7, sub = lane >> 3;
    const int row0 = blockIdx.x * 128;

    const int arow = tid >> 1, akh = (tid & 1) * 16;
    const int bn   = tid & 127, bkh = (tid >> 7) * 16;
    const int gr   = row0 + arow;

    float acc[2][8][4];
#pragma unroll
    for (int i = 0; i < 2; i++)
#pragma unroll
        for (int j = 0; j < 8; j++)
#pragma unroll
            for (int c = 0; c < 4; c++) acc[i][j][c] = 0.f;

    const u32 a_off = (u32)((wm * 32 + lr + (sub & 1) * 8) * 80 + (sub >> 1) * 16);
    const u32 b_off = (u32)((wn * 64 + lr + (sub >> 1) * 8) * 80 + (sub & 1) * 16);

    // ---- prefetch K-slice 0 into registers ----
    float4 aR[4];
    float  bR[16];
    {
        const float* ap = A + (size_t)gr * K + akh;
#pragma unroll
        for (int q = 0; q < 4; q++)
            aR[q] = (gr < M) ? *(const float4*)(ap + q * 4)
                             : make_float4(0.f, 0.f, 0.f, 0.f);
        const float* wp = W + (size_t)bkh * 128 + bn;
#pragma unroll
        for (int q = 0; q < 16; q++) bR[q] = __ldg(wp + q * 128);
    }

    const int niter = K >> 5;
    for (int it = 0; it < niter; it++) {
        const u32 base = sb + (u32)(it & 1) * GEMM_BUF;
        const u32 AHI = base, ALO = base + GEMM_STAGE;
        const u32 BHI = base + 2 * GEMM_STAGE, BLO = base + 3 * GEMM_STAGE;

        // ---- convert staged registers, store to smem[buf] ----
        {
            const u32 dh = AHI + arow * 80 + akh * 2;
            const u32 dl = ALO + arow * 80 + akh * 2;
#pragma unroll
            for (int q = 0; q < 4; q++) {
                float4 v = aR[q];
                u32 h0 = pack_bf2(v.x, v.y);
                u32 h1 = pack_bf2(v.z, v.w);
                float lx = v.x - bf_to_f(h0 & 0xFFFFu);
                float ly = v.y - bf_to_f(h0 >> 16);
                float lz = v.z - bf_to_f(h1 & 0xFFFFu);
                float lw = v.w - bf_to_f(h1 >> 16);
                u32 l0 = pack_bf2(lx, ly);
                u32 l1 = pack_bf2(lz, lw);
                asm volatile("st.shared.v2.b32 [%0], {%1,%2};"
                             :: "r"(dh + q * 8), "r"(h0), "r"(h1));
                asm volatile("st.shared.v2.b32 [%0], {%1,%2};"
                             :: "r"(dl + q * 8), "r"(l0), "r"(l1));
            }
            const u32 dbh = BHI + bn * 80 + bkh * 2;
            const u32 dbl = BLO + bn * 80 + bkh * 2;
#pragma unroll
            for (int q = 0; q < 4; q++) {
                float w0 = bR[4 * q + 0], w1 = bR[4 * q + 1];
                float w2 = bR[4 * q + 2], w3 = bR[4 * q + 3];
                u32 h0 = pack_bf2(w0, w1);
                u32 h1 = pack_bf2(w2, w3);
                float l0f = w0 - bf_to_f(h0 & 0xFFFFu);
                float l1f = w1 - bf_to_f(h0 >> 16);
                float l2f = w2 - bf_to_f(h1 & 0xFFFFu);
                float l3f = w3 - bf_to_f(h1 >> 16);
                u32 l0 = pack_bf2(l0f, l1f);
                u32 l1 = pack_bf2(l2f, l3f);
                asm volatile("st.shared.v2.b32 [%0], {%1,%2};"
                             :: "r"(dbh + q * 8), "r"(h0), "r"(h1));
                asm volatile("st.shared.v2.b32 [%0], {%1,%2};"
                             :: "r"(dbl + q * 8), "r"(l0), "r"(l1));
            }
        }
        __syncthreads();

        // ---- prefetch next K-slice (LDGs overlap the MMAs below) ----
        if (it + 1 < niter) {
            const int k0 = (it + 1) * 32;
            const float* ap = A + (size_t)gr * K + k0 + akh;
#pragma unroll
            for (int q = 0; q < 4; q++)
                aR[q] = (gr < M) ? *(const float4*)(ap + q * 4)
                                 : make_float4(0.f, 0.f, 0.f, 0.f);
            const float* wp = W + (size_t)(k0 + bkh) * 128 + bn;
#pragma unroll
            for (int q = 0; q < 16; q++) bR[q] = __ldg(wp + q * 128);
        }

        // ---- MMA over the 2 k16 chunks, pass-interleaved ----
#pragma unroll
        for (int j = 0; j < 2; j++) {
            u32 ah[2][4], al[2][4];
#pragma unroll
            for (int i = 0; i < 2; i++) {
                const u32 ro = a_off + i * 16 * 80 + j * 32;
                LDM4(ah[i], AHI + ro);
                LDM4(al[i], ALO + ro);
            }
#pragma unroll
            for (int p = 0; p < 4; p++) {
                const u32 bo = b_off + p * 16 * 80 + j * 32;
                u32 bh[4], bl[4];
                LDM4(bh, BHI + bo);
                LDM4(bl, BLO + bo);
                // pass-major interleave: same-acc reuse distance = 4
                MMA16816(acc[0][2 * p],     ah[0], bh[0], bh[1]);
                MMA16816(acc[1][2 * p],     ah[1], bh[0], bh[1]);
                MMA16816(acc[0][2 * p + 1], ah[0], bh[2], bh[3]);
                MMA16816(acc[1][2 * p + 1], ah[1], bh[2], bh[3]);
                MMA16816(acc[0][2 * p],     ah[0], bl[0], bl[1]);
                MMA16816(acc[1][2 * p],     ah[1], bl[0], bl[1]);
                MMA16816(acc[0][2 * p + 1], ah[0], bl[2], bl[3]);
                MMA16816(acc[1][2 * p + 1], ah[1], bl[2], bl[3]);
                MMA16816(acc[0][2 * p],     al[0], bh[0], bh[1]);
                MMA16816(acc[1][2 * p],     al[1], bh[0], bh[1]);
                MMA16816(acc[0][2 * p + 1], al[0], bh[2], bh[3]);
                MMA16816(acc[1][2 * p + 1], al[1], bh[2], bh[3]);
            }
        }
    }

    // ---- epilogue: bias + relu, write C ----
    const int gid = lane >> 2, tig = lane & 3;
#pragma unroll
    for (int i = 0; i < 2; i++) {
        const int ra = row0 + wm * 32 + i * 16 + gid;
        const int rb = ra + 8;
#pragma unroll
        for (int j8 = 0; j8 < 8; j8++) {
            const int col = wn * 64 + j8 * 8 + tig * 2;
            float b0 = __ldg(&bias[col]);
            float b1 = __ldg(&bias[col + 1]);
            if (ra < M) {
                float2 o;
                o.x = fmaxf(acc[i][j8][0] + b0, 0.f);
                o.y = fmaxf(acc[i][j8][1] + b1, 0.f);
                *(float2*)&C[(size_t)ra * 128 + col] = o;
            }
            if (rb < M) {
                float2 o;
                o.x = fmaxf(acc[i][j8][2] + b0, 0.f);
                o.y = fmaxf(acc[i][j8][3] + b1, 0.f);
                *(float2*)&C[(size_t)rb * 128 + col] = o;
            }
        }
    }
}

// ===========================================================================
// Fused CSR build (unchanged)
// ===========================================================================
__global__ __launch_bounds__(256) void hist_all_kernel(
    const int* __restrict__ d11, const int* __restrict__ d22,
    const int* __restrict__ d01, const int* __restrict__ d02,
    int E11, int E22, int E01, int E02,
    int b22, int b01, int b02,
    int* __restrict__ cnt)
{
    int i = blockIdx.x * blockDim.x + threadIdx.x;
    int E12 = E11 + E22, E123 = E12 + E01, E = E123 + E02;
    if (i >= E) return;
    int node;
    if (i < E11)       node =        d11[i];
    else if (i < E12)  node = b22 +  d22[i - E11];
    else if (i < E123) node = b01 +  d01[i - E12];
    else               node = b02 +  d02[i - E123];
    atomicAdd(&cnt[node], 1);
}

#define SCB 1024
__global__ __launch_bounds__(SCB) void scan1_kernel(
    const int* __restrict__ in, int* __restrict__ out, int* __restrict__ bsum, int n)
{
    __shared__ int sh[SCB];
    int i = blockIdx.x * SCB + threadIdx.x;
    int v = (i < n) ? in[i] : 0;
    sh[threadIdx.x] = v;
    __syncthreads();
#pragma unroll
    for (int o = 1; o < SCB; o <<= 1) {
        int t = (threadIdx.x >= o) ? sh[threadIdx.x - o] : 0;
        __syncthreads();
        sh[threadIdx.x] += t;
        __syncthreads();
    }
    if (i < n) out[i] = sh[threadIdx.x] - v;
    if (threadIdx.x == SCB - 1) bsum[blockIdx.x] = sh[threadIdx.x];
}

__global__ __launch_bounds__(SCB) void scan2_kernel(int* __restrict__ bsum, int nb)
{
    __shared__ int sh[SCB];
    int v = (threadIdx.x < nb) ? bsum[threadIdx.x] : 0;
    sh[threadIdx.x] = v;
    __syncthreads();
#pragma unroll
    for (int o = 1; o < SCB; o <<= 1) {
        int t = (threadIdx.x >= o) ? sh[threadIdx.x - o] : 0;
        __syncthreads();
        sh[threadIdx.x] += t;
        __syncthreads();
    }
    if (threadIdx.x < nb) bsum[threadIdx.x] = sh[threadIdx.x] - v;
}

__global__ __launch_bounds__(SCB) void scan3_kernel(
    int* __restrict__ out, const int* __restrict__ bsum, int n)
{
    int i = blockIdx.x * SCB + threadIdx.x;
    if (i < n) out[i] += bsum[blockIdx.x];
}

__global__ __launch_bounds__(256) void fill_all_kernel(
    const int* __restrict__ s11, const int* __restrict__ d11, const float* __restrict__ w11,
    const int* __restrict__ s22, const int* __restrict__ d22, const float* __restrict__ w22,
    const int* __restrict__ s01, const int* __restrict__ d01, const float* __restrict__ w01,
    const int* __restrict__ s02, const int* __restrict__ d02, const float* __restrict__ w02,
    int E11, int E22, int E01, int E02,
    int b22, int b01, int b02,
    const int* __restrict__ ptr, int* __restrict__ fc,
    int* __restrict__ ci, float* __restrict__ wv)
{
    int i = blockIdx.x * blockDim.x + threadIdx.x;
    int E12 = E11 + E22, E123 = E12 + E01, E = E123 + E02;
    if (i >= E) return;
    int node, s; float w;
    if (i < E11)       { node =       d11[i];        s = s11[i];        w = w11[i]; }
    else if (i < E12)  { int j = i - E11;  node = b22 + d22[j]; s = s22[j]; w = w22[j]; }
    else if (i < E123) { int j = i - E12;  node = b01 + d01[j]; s = s01[j]; w = w01[j]; }
    else               { int j = i - E123; node = b02 + d02[j]; s = s02[j]; w = w02[j]; }
    int pos = ptr[node] + atomicAdd(&fc[node], 1);
    ci[pos] = s;
    wv[pos] = w;
}

// ===========================================================================
// Gather SpMM kernels (unchanged)
// ===========================================================================
__global__ __launch_bounds__(256) void gather1_kernel(
    const int* __restrict__ ptr, const int* __restrict__ cnt,
    const int* __restrict__ ci, const float* __restrict__ wv,
    const float* __restrict__ x, float* __restrict__ out, int N)
{
    int t = blockIdx.x * blockDim.x + threadIdx.x;
    int n = t >> 5;
    if (n >= N) return;
    int lane = t & 31;

    int beg = __ldg(&ptr[n]);
    int end = beg + __ldg(&cnt[n]);
    float4 acc = make_float4(0.f, 0.f, 0.f, 0.f);

    int e = beg;
    for (; e + 4 <= end; e += 4) {
        int s0 = __ldg(&ci[e]),   s1 = __ldg(&ci[e+1]);
        int s2 = __ldg(&ci[e+2]), s3 = __ldg(&ci[e+3]);
        float w0 = __ldg(&wv[e]),   w1 = __ldg(&wv[e+1]);
        float w2 = __ldg(&wv[e+2]), w3 = __ldg(&wv[e+3]);
        float4 v0 = *(const float4*)&x[(size_t)s0 * 128 + lane * 4];
        float4 v1 = *(const float4*)&x[(size_t)s1 * 128 + lane * 4];
        float4 v2 = *(const float4*)&x[(size_t)s2 * 128 + lane * 4];
        float4 v3 = *(const float4*)&x[(size_t)s3 * 128 + lane * 4];
        acc.x = fmaf(w0, v0.x, fmaf(w1, v1.x, fmaf(w2, v2.x, fmaf(w3, v3.x, acc.x))));
        acc.y = fmaf(w0, v0.y, fmaf(w1, v1.y, fmaf(w2, v2.y, fmaf(w3, v3.y, acc.y))));
        acc.z = fmaf(w0, v0.z, fmaf(w1, v1.z, fmaf(w2, v2.z, fmaf(w3, v3.z, acc.z))));
        acc.w = fmaf(w0, v0.w, fmaf(w1, v1.w, fmaf(w2, v2.w, fmaf(w3, v3.w, acc.w))));
    }
    for (; e < end; e++) {
        int s = __ldg(&ci[e]);
        float w0 = __ldg(&wv[e]);
        float4 v = *(const float4*)&x[(size_t)s * 128 + lane * 4];
        acc.x = fmaf(w0, v.x, acc.x);
        acc.y = fmaf(w0, v.y, acc.y);
        acc.z = fmaf(w0, v.z, acc.z);
        acc.w = fmaf(w0, v.w, acc.w);
    }
    *(float4*)&out[(size_t)n * 128 + lane * 4] = acc;
}

__global__ __launch_bounds__(256) void gather2_kernel(
    const int* __restrict__ ptr, const int* __restrict__ cnt,
    const int* __restrict__ ci, const float* __restrict__ wv,
    const float* __restrict__ x0, const float* __restrict__ x1,
    float* __restrict__ o0, float* __restrict__ o1, int N)
{
    int t = blockIdx.x * blockDim.x + threadIdx.x;
    int n = t >> 5;
    if (n >= N) return;
    int lane = t & 31;

    int beg = __ldg(&ptr[n]);
    int end = beg + __ldg(&cnt[n]);
    float4 a0 = make_float4(0.f, 0.f, 0.f, 0.f);
    float4 a1 = a0;

    int e = beg;
    for (; e + 2 <= end; e += 2) {
        int sA = __ldg(&ci[e]), sB = __ldg(&ci[e+1]);
        float wA = __ldg(&wv[e]), wB = __ldg(&wv[e+1]);
        size_t oA = (size_t)sA * 128 + lane * 4;
        size_t oB = (size_t)sB * 128 + lane * 4;
        float4 vA0 = *(const float4*)&x0[oA];
        float4 vB0 = *(const float4*)&x0[oB];
        float4 vA1 = *(const float4*)&x1[oA];
        float4 vB1 = *(const float4*)&x1[oB];
        a0.x = fmaf(wA, vA0.x, fmaf(wB, vB0.x, a0.x));
        a0.y = fmaf(wA, vA0.y, fmaf(wB, vB0.y, a0.y));
        a0.z = fmaf(wA, vA0.z, fmaf(wB, vB0.z, a0.z));
        a0.w = fmaf(wA, vA0.w, fmaf(wB, vB0.w, a0.w));
        a1.x = fmaf(wA, vA1.x, fmaf(wB, vB1.x, a1.x));
        a1.y = fmaf(wA, vA1.y, fmaf(wB, vB1.y, a1.y));
        a1.z = fmaf(wA, vA1.z, fmaf(wB, vB1.z, a1.z));
        a1.w = fmaf(wA, vA1.w, fmaf(wB, vB1.w, a1.w));
    }
    for (; e < end; e++) {
        int s = __ldg(&ci[e]);
        float w0 = __ldg(&wv[e]);
        size_t o = (size_t)s * 128 + lane * 4;
        float4 v0 = *(const float4*)&x0[o];
        float4 v1 = *(const float4*)&x1[o];
        a0.x = fmaf(w0, v0.x, a0.x); a0.y = fmaf(w0, v0.y, a0.y);
        a0.z = fmaf(w0, v0.z, a0.z); a0.w = fmaf(w0, v0.w, a0.w);
        a1.x = fmaf(w0, v1.x, a1.x); a1.y = fmaf(w0, v1.y, a1.y);
        a1.z = fmaf(w0, v1.z, a1.z); a1.w = fmaf(w0, v1.w, a1.w);
    }
    size_t od = (size_t)n * 128 + lane * 4;
    *(float4*)&o0[od] = a0;
    *(float4*)&o1[od] = a1;
}

__global__ __launch_bounds__(256) void gather3_kernel(
    const int* __restrict__ ptr, const int* __restrict__ cnt,
    const int* __restrict__ ci, const float* __restrict__ wv,
    const float* __restrict__ x0, const float* __restrict__ x1,
    const float* __restrict__ x2,
    float* __restrict__ o0, float* __restrict__ o1, float* __restrict__ o2, int N)
{
    int t = blockIdx.x * blockDim.x + threadIdx.x;
    int n = t >> 5;
    if (n >= N) return;
    int lane = t & 31;

    int beg = __ldg(&ptr[n]);
    int end = beg + __ldg(&cnt[n]);
    float4 a0 = make_float4(0.f, 0.f, 0.f, 0.f);
    float4 a1 = a0, a2 = a0;

    int e = beg;
    for (; e + 2 <= end; e += 2) {
        int sA = __ldg(&ci[e]), sB = __ldg(&ci[e+1]);
        float wA = __ldg(&wv[e]), wB = __ldg(&wv[e+1]);
        size_t oA = (size_t)sA * 128 + lane * 4;
        size_t oB = (size_t)sB * 128 + lane * 4;
        float4 vA0 = *(const float4*)&x0[oA];
        float4 vB0 = *(const float4*)&x0[oB];
        float4 vA1 = *(const float4*)&x1[oA];
        float4 vB1 = *(const float4*)&x1[oB];
        float4 vA2 = *(const float4*)&x2[oA];
        float4 vB2 = *(const float4*)&x2[oB];
        a0.x = fmaf(wA, vA0.x, fmaf(wB, vB0.x, a0.x));
        a0.y = fmaf(wA, vA0.y, fmaf(wB, vB0.y, a0.y));
        a0.z = fmaf(wA, vA0.z, fmaf(wB, vB0.z, a0.z));
        a0.w = fmaf(wA, vA0.w, fmaf(wB, vB0.w, a0.w));
        a1.x = fmaf(wA, vA1.x, fmaf(wB, vB1.x, a1.x));
        a1.y = fmaf(wA, vA1.y, fmaf(wB, vB1.y, a1.y));
        a1.z = fmaf(wA, vA1.z, fmaf(wB, vB1.z, a1.z));
        a1.w = fmaf(wA, vA1.w, fmaf(wB, vB1.w, a1.w));
        a2.x = fmaf(wA, vA2.x, fmaf(wB, vB2.x, a2.x));
        a2.y = fmaf(wA, vA2.y, fmaf(wB, vB2.y, a2.y));
        a2.z = fmaf(wA, vA2.z, fmaf(wB, vB2.z, a2.z));
        a2.w = fmaf(wA, vA2.w, fmaf(wB, vB2.w, a2.w));
    }
    for (; e < end; e++) {
        int s = __ldg(&ci[e]);
        float w0 = __ldg(&wv[e]);
        size_t o = (size_t)s * 128 + lane * 4;
        float4 v0 = *(const float4*)&x0[o];
        float4 v1 = *(const float4*)&x1[o];
        float4 v2 = *(const float4*)&x2[o];
        a0.x = fmaf(w0, v0.x, a0.x); a0.y = fmaf(w0, v0.y, a0.y);
        a0.z = fmaf(w0, v0.z, a0.z); a0.w = fmaf(w0, v0.w, a0.w);
        a1.x = fmaf(w0, v1.x, a1.x); a1.y = fmaf(w0, v1.y, a1.y);
        a1.z = fmaf(w0, v1.z, a1.z); a1.w = fmaf(w0, v1.w, a1.w);
        a2.x = fmaf(w0, v2.x, a2.x); a2.y = fmaf(w0, v2.y, a2.y);
        a2.z = fmaf(w0, v2.z, a2.z); a2.w = fmaf(w0, v2.w, a2.w);
    }
    size_t od = (size_t)n * 128 + lane * 4;
    *(float4*)&o0[od] = a0;
    *(float4*)&o1[od] = a1;
    *(float4*)&o2[od] = a2;
}

// ===========================================================================
// Final epilogue (unchanged)
// ===========================================================================
__global__ __launch_bounds__(128) void finalize_kernel(
    const float* __restrict__ r0, const float* __restrict__ rA,
    const float* __restrict__ rw, const float* __restrict__ r0s,
    const float* __restrict__ rB, float* __restrict__ out)
{
    const int n = blockIdx.x;
    const int t = threadIdx.x;
    const int lane = t & 31, wid = t >> 5;

    const size_t base = (size_t)n * 128 + t;
    float v0  = r0 [base];
    float vA  = rA [base];
    float vW  = rw [base];
    float v0s = r0s[base];
    float vB  = rB [base];

    float4 sq = make_float4(v0 * v0, vA * vA + vW * vW,
                            v0s * v0s, vB * vB + vW * vW);
#pragma unroll
    for (int o = 16; o; o >>= 1) {
        sq.x += __shfl_xor_sync(0xffffffffu, sq.x, o);
        sq.y += __shfl_xor_sync(0xffffffffu, sq.y, o);
        sq.z += __shfl_xor_sync(0xffffffffu, sq.z, o);
        sq.w += __shfl_xor_sync(0xffffffffu, sq.w, o);
    }
    __shared__ float4 wsum[4];
    if (lane == 0) wsum[wid] = sq;
    __syncthreads();
    float s0  = wsum[0].x + wsum[1].x + wsum[2].x + wsum[3].x;
    float s1  = wsum[0].y + wsum[1].y + wsum[2].y + wsum[3].y;
    float s0s = wsum[0].z + wsum[1].z + wsum[2].z + wsum[3].z;
    float s1s = wsum[0].w + wsum[1].w + wsum[2].w + wsum[3].w;

    const float EPS = 1e-9f;
    float i0  = 1.f / (sqrtf(s0)  + EPS);
    float i1  = 1.f / (sqrtf(s1)  + EPS);
    float i0s = 1.f / (sqrtf(s0s) + EPS);
    float i1s = 1.f / (sqrtf(s1s) + EPS);

    size_t drow = (size_t)n * 384;
    out[drow + t]       = v0 * i0;
    out[drow + 128 + t] = vA * i1;
    out[drow + 256 + t] = vW * i1;

    size_t srow = (size_t)N0_DOCS * 384 + drow;
    out[srow + t]       = v0s * i0s;
    out[srow + 128 + t] = vB * i1s;
    out[srow + 256 + t] = vW * i1s;
}

// ===========================================================================
// Launch
// ===========================================================================
extern "C" void kernel_launch(void* const* d_in, const int* in_sizes, int n_in,
                              void* d_out, int out_size)
{
    const float* x1       = (const float*)d_in[0];
    const float* x2       = (const float*)d_in[1];
    const float* word_emb = (const float*)d_in[2];
    const float* W1a = (const float*)d_in[3];
    const float* b1a = (const float*)d_in[4];
    const float* W1b = (const float*)d_in[5];
    const float* b1b = (const float*)d_in[6];
    const float* W2a = (const float*)d_in[7];
    const float* b2a = (const float*)d_in[8];
    const float* W2b = (const float*)d_in[9];
    const float* b2b = (const float*)d_in[10];
    const int*   e11_src = (const int*)d_in[11];
    const int*   e11_dst = (const int*)d_in[12];
    const float* e11_w   = (const float*)d_in[13];
    const int*   e22_src = (const int*)d_in[14];
    const int*   e22_dst = (const int*)d_in[15];
    const float* e22_w   = (const float*)d_in[16];
    const int*   e01_src = (const int*)d_in[17];
    const int*   e01_dst = (const int*)d_in[18];
    const float* e01_w   = (const float*)d_in[19];
    const int*   e02_src = (const int*)d_in[20];
    const int*   e02_dst = (const int*)d_in[21];
    const float* e02_w   = (const float*)d_in[22];

    const int N1  = in_sizes[0] / 256;
    const int N2  = in_sizes[1] / 256;
    const int E11 = in_sizes[11];
    const int E22 = in_sizes[14];
    const int E01 = in_sizes[17];
    const int E02 = in_sizes[20];
    const int Etot = E11 + E22 + E01 + E02;
    const int Ntot = N1 + N2 + 2 * N0_DOCS;
    const int b22 = N1, b01 = N1 + N2, b02 = N1 + N2 + N0_DOCS;

    float *l1_1, *h1, *l2_1, *l1_2, *h2, *l2_2, *r0, *r0s, *rA, *rB, *rw;
    cudaGetSymbolAddress((void**)&l1_1, g_l1_1);
    cudaGetSymbolAddress((void**)&h1,   g_h1);
    cudaGetSymbolAddress((void**)&l2_1, g_l2_1);
    cudaGetSymbolAddress((void**)&l1_2, g_l1_2);
    cudaGetSymbolAddress((void**)&h2,   g_h2);
    cudaGetSymbolAddress((void**)&l2_2, g_l2_2);
    cudaGetSymbolAddress((void**)&r0,   g_r0);
    cudaGetSymbolAddress((void**)&r0s,  g_r0s);
    cudaGetSymbolAddress((void**)&rA,   g_rA);
    cudaGetSymbolAddress((void**)&rB,   g_rB);
    cudaGetSymbolAddress((void**)&rw,   g_rw);

    int *cntfc, *ptr, *ci, *bsum;
    float *wv;
    cudaGetSymbolAddress((void**)&cntfc, g_cntfc);
    cudaGetSymbolAddress((void**)&ptr,   g_ptr);
    cudaGetSymbolAddress((void**)&ci,    g_ci);
    cudaGetSymbolAddress((void**)&wv,    g_wv);
    cudaGetSymbolAddress((void**)&bsum,  g_bsum);
    int* cnt = cntfc;
    int* fc  = cntfc + NTOT;

    static cudaStream_t s1 = nullptr, s2 = nullptr, s3 = nullptr;
    static cudaEvent_t ev0 = nullptr, ev1 = nullptr, ev2 = nullptr, ecsr = nullptr;
    if (s1 == nullptr) {
        cudaStreamCreateWithFlags(&s1, cudaStreamNonBlocking);
        cudaStreamCreateWithFlags(&s2, cudaStreamNonBlocking);
        cudaStreamCreateWithFlags(&s3, cudaStreamNonBlocking);
        cudaEventCreateWithFlags(&ev0, cudaEventDisableTiming);
        cudaEventCreateWithFlags(&ev1, cudaEventDisableTiming);
        cudaEventCreateWithFlags(&ev2, cudaEventDisableTiming);
        cudaEventCreateWithFlags(&ecsr, cudaEventDisableTiming);
        cudaFuncSetAttribute(gemm_mma_kernel,
                             cudaFuncAttributeMaxDynamicSharedMemorySize, GEMM_SMEM);
    }

    // Fork
    cudaEventRecord(ev0, 0);
    cudaStreamWaitEvent(s1, ev0, 0);
    cudaStreamWaitEvent(s2, ev0, 0);
    cudaStreamWaitEvent(s3, ev0, 0);

    // ---- stream 3: fused CSR build ----
    cudaMemsetAsync(cntfc, 0, 2 * NTOT * sizeof(int), s3);
    hist_all_kernel<<<(Etot + 255) / 256, 256, 0, s3>>>(
        e11_dst, e22_dst, e01_dst, e02_dst, E11, E22, E01, E02,
        b22, b01, b02, cnt);
    int nb = (Ntot + SCB - 1) / SCB;
    scan1_kernel<<<nb, SCB, 0, s3>>>(cnt, ptr, bsum, Ntot);
    scan2_kernel<<<1, SCB, 0, s3>>>(bsum, nb);
    scan3_kernel<<<nb, SCB, 0, s3>>>(ptr, bsum, Ntot);
    fill_all_kernel<<<(Etot + 255) / 256, 256, 0, s3>>>(
        e11_src, e11_dst, e11_w, e22_src, e22_dst, e22_w,
        e01_src, e01_dst, e01_w, e02_src, e02_dst, e02_w,
        E11, E22, E01, E02, b22, b01, b02, ptr, fc, ci, wv);
    cudaEventRecord(ecsr, s3);

    // ---- stream 1: type-1 pipeline ----
    gemm_mma_kernel<<<(N1 + 127) / 128, 256, GEMM_SMEM, s1>>>(x1, W1a, b1a, l1_1, N1, 256);
    cudaStreamWaitEvent(s1, ecsr, 0);
    gather1_kernel<<<(N1 * 32 + 255) / 256, 256, 0, s1>>>(
        ptr, cnt, ci, wv, l1_1, h1, N1);
    gemm_mma_kernel<<<(N1 + 127) / 128, 256, GEMM_SMEM, s1>>>(h1, W1b, b1b, l2_1, N1, 128);
    gather2_kernel<<<(N0_DOCS * 32 + 255) / 256, 256, 0, s1>>>(
        ptr + b01, cnt + b01, ci, wv, l2_1, l1_1, r0, r0s, N0_DOCS);
    cudaEventRecord(ev1, s1);

    // ---- stream 2: type-2 pipeline ----
    gemm_mma_kernel<<<(N2 + 127) / 128, 256, GEMM_SMEM, s2>>>(x2, W2a, b2a, l1_2, N2, 256);
    cudaStreamWaitEvent(s2, ecsr, 0);
    gather1_kernel<<<(N2 * 32 + 255) / 256, 256, 0, s2>>>(
        ptr + b22, cnt + b22, ci, wv, l1_2, h2, N2);
    gemm_mma_kernel<<<(N2 + 127) / 128, 256, GEMM_SMEM, s2>>>(h2, W2b, b2b, l2_2, N2, 128);
    gather3_kernel<<<(N0_DOCS * 32 + 255) / 256, 256, 0, s2>>>(
        ptr + b02, cnt + b02, ci, wv, l2_2, l1_2, word_emb, rA, rB, rw, N0_DOCS);
    cudaEventRecord(ev2, s2);

    // ---- join + finalize ----
    cudaStreamWaitEvent(0, ev1, 0);
    cudaStreamWaitEvent(0, ev2, 0);
    finalize_kernel<<<N0_DOCS, 128, 0, 0>>>(r0, rA, rw, r0s, rB, (float*)d_out);
}

// round 8
// speedup vs baseline: 2.8430x; 1.0818x over previous
#include <cuda_runtime.h>
#include <cuda_bf16.h>
#include <math.h>

typedef unsigned long long ull;
typedef unsigned int u32;

#define N0_DOCS 10000
#define MAXN1 50000
#define MAXN2 30000
#define NTOT (MAXN1 + MAXN2 + 2 * N0_DOCS)
#define ETOT (800000 + 480000 + 320000 + 160000)

// ---------------- feature scratch ----------------
// l1/l2 feature buffers in packed bf16x2 (64 u32 per 128-wide row)
__device__ u32   g_l1_1[MAXN1 * 64];
__device__ u32   g_l2_1[MAXN1 * 64];
__device__ u32   g_l1_2[MAXN2 * 64];
__device__ u32   g_l2_2[MAXN2 * 64];
__device__ float g_h1  [MAXN1 * 128];
__device__ float g_h2  [MAXN2 * 128];
__device__ float g_r0 [N0_DOCS * 128];
__device__ float g_r0s[N0_DOCS * 128];
__device__ float g_rA [N0_DOCS * 128];
__device__ float g_rB [N0_DOCS * 128];
__device__ float g_rw [N0_DOCS * 128];

// ---------------- CSR scratch ----------------
__device__ int   g_cntfc[2 * NTOT];
__device__ int   g_ptr[NTOT];
__device__ int   g_ci[ETOT];
__device__ float g_wv[ETOT];
__device__ int   g_bsum[128];

// ---------------------------------------------------------------------------
// helpers
// ---------------------------------------------------------------------------
__device__ __forceinline__ u32 smem_u32(const void* p) {
    u32 a;
    asm("{ .reg .u64 t; cvta.to.shared.u64 t, %1; cvt.u32.u64 %0, t; }"
        : "=r"(a) : "l"(p));
    return a;
}
__device__ __forceinline__ u32 pack_bf2(float a, float b) {
    u32 r;
    asm("cvt.rn.bf16x2.f32 %0, %1, %2;" : "=r"(r) : "f"(b), "f"(a));
    return r;
}
__device__ __forceinline__ float bf_to_f(u32 lo16) {
    return __uint_as_float(lo16 << 16);
}
// unpack bf16x2 -> (lo, hi) floats
__device__ __forceinline__ float2 bf2f(u32 p) {
    float2 r;
    r.x = __uint_as_float(p << 16);
    r.y = __uint_as_float(p & 0xFFFF0000u);
    return r;
}

#define LDM4(r, addr)                                                          \
    asm volatile("ldmatrix.sync.aligned.m8n8.x4.shared.b16 {%0,%1,%2,%3}, [%4];" \
                 : "=r"((r)[0]), "=r"((r)[1]), "=r"((r)[2]), "=r"((r)[3])      \
                 : "r"(addr))

#define MMA16816(c, a, b0v, b1v)                                               \
    asm volatile("mma.sync.aligned.m16n8k16.row.col.f32.bf16.bf16.f32 "        \
                 "{%0,%1,%2,%3}, {%4,%5,%6,%7}, {%8,%9}, {%0,%1,%2,%3};"       \
                 : "+f"((c)[0]), "+f"((c)[1]), "+f"((c)[2]), "+f"((c)[3])      \
                 : "r"((a)[0]), "r"((a)[1]), "r"((a)[2]), "r"((a)[3]),         \
                   "r"(b0v), "r"(b1v))

#define GEMM_STAGE 10240
#define GEMM_BUF   (4 * GEMM_STAGE)
#define GEMM_SMEM  (2 * GEMM_BUF)

// ===========================================================================
// Pipelined mma.sync bf16 hi/lo GEMM + bias + ReLU.
// OBF=0: C is float[M,128].  OBF=1: C is packed bf16x2 u32[M,64].
// ===========================================================================
template <int OBF>
__global__ __launch_bounds__(256) void gemm_mma_kernel(
    const float* __restrict__ A, const float* __restrict__ W,
    const float* __restrict__ bias, void* __restrict__ Cv,
    int M, int K)
{
    extern __shared__ __align__(16) unsigned char smbuf[];
    const u32 sb = smem_u32(smbuf);

    const int tid  = threadIdx.x;
    const int lane = tid & 31, wid = tid >> 5;
    const int wm = wid & 3, wn = wid >> 2;
    const int lr = lane & 7, sub = lane >> 3;
    const int row0 = blockIdx.x * 128;

    const int arow = tid >> 1, akh = (tid & 1) * 16;
    const int bn   = tid & 127, bkh = (tid >> 7) * 16;
    const int gr   = row0 + arow;

    float acc[2][8][4];
#pragma unroll
    for (int i = 0; i < 2; i++)
#pragma unroll
        for (int j = 0; j < 8; j++)
#pragma unroll
            for (int c = 0; c < 4; c++) acc[i][j][c] = 0.f;

    const u32 a_off = (u32)((wm * 32 + lr + (sub & 1) * 8) * 80 + (sub >> 1) * 16);
    const u32 b_off = (u32)((wn * 64 + lr + (sub >> 1) * 8) * 80 + (sub & 1) * 16);

    float4 aR[4];
    float  bR[16];
    {
        const float* ap = A + (size_t)gr * K + akh;
#pragma unroll
        for (int q = 0; q < 4; q++)
            aR[q] = (gr < M) ? *(const float4*)(ap + q * 4)
                             : make_float4(0.f, 0.f, 0.f, 0.f);
        const float* wp = W + (size_t)bkh * 128 + bn;
#pragma unroll
        for (int q = 0; q < 16; q++) bR[q] = __ldg(wp + q * 128);
    }

    const int niter = K >> 5;
    for (int it = 0; it < niter; it++) {
        const u32 base = sb + (u32)(it & 1) * GEMM_BUF;
        const u32 AHI = base, ALO = base + GEMM_STAGE;
        const u32 BHI = base + 2 * GEMM_STAGE, BLO = base + 3 * GEMM_STAGE;

        {
            const u32 dh = AHI + arow * 80 + akh * 2;
            const u32 dl = ALO + arow * 80 + akh * 2;
#pragma unroll
            for (int q = 0; q < 4; q++) {
                float4 v = aR[q];
                u32 h0 = pack_bf2(v.x, v.y);
                u32 h1 = pack_bf2(v.z, v.w);
                float lx = v.x - bf_to_f(h0 & 0xFFFFu);
                float ly = v.y - bf_to_f(h0 >> 16);
                float lz = v.z - bf_to_f(h1 & 0xFFFFu);
                float lw = v.w - bf_to_f(h1 >> 16);
                u32 l0 = pack_bf2(lx, ly);
                u32 l1 = pack_bf2(lz, lw);
                asm volatile("st.shared.v2.b32 [%0], {%1,%2};"
                             :: "r"(dh + q * 8), "r"(h0), "r"(h1));
                asm volatile("st.shared.v2.b32 [%0], {%1,%2};"
                             :: "r"(dl + q * 8), "r"(l0), "r"(l1));
            }
            const u32 dbh = BHI + bn * 80 + bkh * 2;
            const u32 dbl = BLO + bn * 80 + bkh * 2;
#pragma unroll
            for (int q = 0; q < 4; q++) {
                float w0 = bR[4 * q + 0], w1 = bR[4 * q + 1];
                float w2 = bR[4 * q + 2], w3 = bR[4 * q + 3];
                u32 h0 = pack_bf2(w0, w1);
                u32 h1 = pack_bf2(w2, w3);
                float l0f = w0 - bf_to_f(h0 & 0xFFFFu);
                float l1f = w1 - bf_to_f(h0 >> 16);
                float l2f = w2 - bf_to_f(h1 & 0xFFFFu);
                float l3f = w3 - bf_to_f(h1 >> 16);
                u32 l0 = pack_bf2(l0f, l1f);
                u32 l1 = pack_bf2(l2f, l3f);
                asm volatile("st.shared.v2.b32 [%0], {%1,%2};"
                             :: "r"(dbh + q * 8), "r"(h0), "r"(h1));
                asm volatile("st.shared.v2.b32 [%0], {%1,%2};"
                             :: "r"(dbl + q * 8), "r"(l0), "r"(l1));
            }
        }
        __syncthreads();

        if (it + 1 < niter) {
            const int k0 = (it + 1) * 32;
            const float* ap = A + (size_t)gr * K + k0 + akh;
#pragma unroll
            for (int q = 0; q < 4; q++)
                aR[q] = (gr < M) ? *(const float4*)(ap + q * 4)
                                 : make_float4(0.f, 0.f, 0.f, 0.f);
            const float* wp = W + (size_t)(k0 + bkh) * 128 + bn;
#pragma unroll
            for (int q = 0; q < 16; q++) bR[q] = __ldg(wp + q * 128);
        }

#pragma unroll
        for (int j = 0; j < 2; j++) {
            u32 ah[2][4], al[2][4];
#pragma unroll
            for (int i = 0; i < 2; i++) {
                const u32 ro = a_off + i * 16 * 80 + j * 32;
                LDM4(ah[i], AHI + ro);
                LDM4(al[i], ALO + ro);
            }
#pragma unroll
            for (int p = 0; p < 4; p++) {
                const u32 bo = b_off + p * 16 * 80 + j * 32;
                u32 bh[4], bl[4];
                LDM4(bh, BHI + bo);
                LDM4(bl, BLO + bo);
                MMA16816(acc[0][2 * p],     ah[0], bh[0], bh[1]);
                MMA16816(acc[1][2 * p],     ah[1], bh[0], bh[1]);
                MMA16816(acc[0][2 * p + 1], ah[0], bh[2], bh[3]);
                MMA16816(acc[1][2 * p + 1], ah[1], bh[2], bh[3]);
                MMA16816(acc[0][2 * p],     ah[0], bl[0], bl[1]);
                MMA16816(acc[1][2 * p],     ah[1], bl[0], bl[1]);
                MMA16816(acc[0][2 * p + 1], ah[0], bl[2], bl[3]);
                MMA16816(acc[1][2 * p + 1], ah[1], bl[2], bl[3]);
                MMA16816(acc[0][2 * p],     al[0], bh[0], bh[1]);
                MMA16816(acc[1][2 * p],     al[1], bh[0], bh[1]);
                MMA16816(acc[0][2 * p + 1], al[0], bh[2], bh[3]);
                MMA16816(acc[1][2 * p + 1], al[1], bh[2], bh[3]);
            }
        }
    }

    // ---- epilogue ----
    const int gid = lane >> 2, tig = lane & 3;
#pragma unroll
    for (int i = 0; i < 2; i++) {
        const int ra = row0 + wm * 32 + i * 16 + gid;
        const int rb = ra + 8;
#pragma unroll
        for (int j8 = 0; j8 < 8; j8++) {
            const int col = wn * 64 + j8 * 8 + tig * 2;
            float b0 = __ldg(&bias[col]);
            float b1 = __ldg(&bias[col + 1]);
            float oa0 = fmaxf(acc[i][j8][0] + b0, 0.f);
            float oa1 = fmaxf(acc[i][j8][1] + b1, 0.f);
            float ob0 = fmaxf(acc[i][j8][2] + b0, 0.f);
            float ob1 = fmaxf(acc[i][j8][3] + b1, 0.f);
            if (OBF) {
                u32* Cb = (u32*)Cv;
                if (ra < M) Cb[(size_t)ra * 64 + (col >> 1)] = pack_bf2(oa0, oa1);
                if (rb < M) Cb[(size_t)rb * 64 + (col >> 1)] = pack_bf2(ob0, ob1);
            } else {
                float* Cf = (float*)Cv;
                if (ra < M) { float2 o; o.x = oa0; o.y = oa1;
                              *(float2*)&Cf[(size_t)ra * 128 + col] = o; }
                if (rb < M) { float2 o; o.x = ob0; o.y = ob1;
                              *(float2*)&Cf[(size_t)rb * 128 + col] = o; }
            }
        }
    }
}

// ===========================================================================
// Fused CSR build (unchanged)
// ===========================================================================
__global__ __launch_bounds__(256) void hist_all_kernel(
    const int* __restrict__ d11, const int* __restrict__ d22,
    const int* __restrict__ d01, const int* __restrict__ d02,
    int E11, int E22, int E01, int E02,
    int b22, int b01, int b02,
    int* __restrict__ cnt)
{
    int i = blockIdx.x * blockDim.x + threadIdx.x;
    int E12 = E11 + E22, E123 = E12 + E01, E = E123 + E02;
    if (i >= E) return;
    int node;
    if (i < E11)       node =        d11[i];
    else if (i < E12)  node = b22 +  d22[i - E11];
    else if (i < E123) node = b01 +  d01[i - E12];
    else               node = b02 +  d02[i - E123];
    atomicAdd(&cnt[node], 1);
}

#define SCB 1024
__global__ __launch_bounds__(SCB) void scan1_kernel(
    const int* __restrict__ in, int* __restrict__ out, int* __restrict__ bsum, int n)
{
    __shared__ int sh[SCB];
    int i = blockIdx.x * SCB + threadIdx.x;
    int v = (i < n) ? in[i] : 0;
    sh[threadIdx.x] = v;
    __syncthreads();
#pragma unroll
    for (int o = 1; o < SCB; o <<= 1) {
        int t = (threadIdx.x >= o) ? sh[threadIdx.x - o] : 0;
        __syncthreads();
        sh[threadIdx.x] += t;
        __syncthreads();
    }
    if (i < n) out[i] = sh[threadIdx.x] - v;
    if (threadIdx.x == SCB - 1) bsum[blockIdx.x] = sh[threadIdx.x];
}

__global__ __launch_bounds__(SCB) void scan2_kernel(int* __restrict__ bsum, int nb)
{
    __shared__ int sh[SCB];
    int v = (threadIdx.x < nb) ? bsum[threadIdx.x] : 0;
    sh[threadIdx.x] = v;
    __syncthreads();
#pragma unroll
    for (int o = 1; o < SCB; o <<= 1) {
        int t = (threadIdx.x >= o) ? sh[threadIdx.x - o] : 0;
        __syncthreads();
        sh[threadIdx.x] += t;
        __syncthreads();
    }
    if (threadIdx.x < nb) bsum[threadIdx.x] = sh[threadIdx.x] - v;
}

__global__ __launch_bounds__(SCB) void scan3_kernel(
    int* __restrict__ out, const int* __restrict__ bsum, int n)
{
    int i = blockIdx.x * SCB + threadIdx.x;
    if (i < n) out[i] += bsum[blockIdx.x];
}

__global__ __launch_bounds__(256) void fill_all_kernel(
    const int* __restrict__ s11, const int* __restrict__ d11, const float* __restrict__ w11,
    const int* __restrict__ s22, const int* __restrict__ d22, const float* __restrict__ w22,
    const int* __restrict__ s01, const int* __restrict__ d01, const float* __restrict__ w01,
    const int* __restrict__ s02, const int* __restrict__ d02, const float* __restrict__ w02,
    int E11, int E22, int E01, int E02,
    int b22, int b01, int b02,
    const int* __restrict__ ptr, int* __restrict__ fc,
    int* __restrict__ ci, float* __restrict__ wv)
{
    int i = blockIdx.x * blockDim.x + threadIdx.x;
    int E12 = E11 + E22, E123 = E12 + E01, E = E123 + E02;
    if (i >= E) return;
    int node, s; float w;
    if (i < E11)       { node =       d11[i];        s = s11[i];        w = w11[i]; }
    else if (i < E12)  { int j = i - E11;  node = b22 + d22[j]; s = s22[j]; w = w22[j]; }
    else if (i < E123) { int j = i - E12;  node = b01 + d01[j]; s = s01[j]; w = w01[j]; }
    else               { int j = i - E123; node = b02 + d02[j]; s = s02[j]; w = w02[j]; }
    int pos = ptr[node] + atomicAdd(&fc[node], 1);
    ci[pos] = s;
    wv[pos] = w;
}

// ===========================================================================
// Gather SpMM kernels — bf16 feature reads, fp32 accumulate/write
// ===========================================================================
__device__ __forceinline__ void acc_bf2(float4& a, uint2 u, float w) {
    float2 p0 = bf2f(u.x), p1 = bf2f(u.y);
    a.x = fmaf(w, p0.x, a.x);
    a.y = fmaf(w, p0.y, a.y);
    a.z = fmaf(w, p1.x, a.z);
    a.w = fmaf(w, p1.y, a.w);
}

// out(fp32)[n] = sum w * x_bf16[src]
__global__ __launch_bounds__(256) void gather1_kernel(
    const int* __restrict__ ptr, const int* __restrict__ cnt,
    const int* __restrict__ ci, const float* __restrict__ wv,
    const u32* __restrict__ x, float* __restrict__ out, int N)
{
    int t = blockIdx.x * blockDim.x + threadIdx.x;
    int n = t >> 5;
    if (n >= N) return;
    int lane = t & 31;

    int beg = __ldg(&ptr[n]);
    int end = beg + __ldg(&cnt[n]);
    float4 acc = make_float4(0.f, 0.f, 0.f, 0.f);

    int e = beg;
    for (; e + 4 <= end; e += 4) {
        int s0 = __ldg(&ci[e]),   s1 = __ldg(&ci[e+1]);
        int s2 = __ldg(&ci[e+2]), s3 = __ldg(&ci[e+3]);
        float w0 = __ldg(&wv[e]),   w1 = __ldg(&wv[e+1]);
        float w2 = __ldg(&wv[e+2]), w3 = __ldg(&wv[e+3]);
        uint2 v0 = *(const uint2*)&x[(size_t)s0 * 64 + lane * 2];
        uint2 v1 = *(const uint2*)&x[(size_t)s1 * 64 + lane * 2];
        uint2 v2 = *(const uint2*)&x[(size_t)s2 * 64 + lane * 2];
        uint2 v3 = *(const uint2*)&x[(size_t)s3 * 64 + lane * 2];
        acc_bf2(acc, v0, w0);
        acc_bf2(acc, v1, w1);
        acc_bf2(acc, v2, w2);
        acc_bf2(acc, v3, w3);
    }
    for (; e < end; e++) {
        int s = __ldg(&ci[e]);
        float w0 = __ldg(&wv[e]);
        uint2 v = *(const uint2*)&x[(size_t)s * 64 + lane * 2];
        acc_bf2(acc, v, w0);
    }
    *(float4*)&out[(size_t)n * 128 + lane * 4] = acc;
}

__global__ __launch_bounds__(256) void gather2_kernel(
    const int* __restrict__ ptr, const int* __restrict__ cnt,
    const int* __restrict__ ci, const float* __restrict__ wv,
    const u32* __restrict__ x0, const u32* __restrict__ x1,
    float* __restrict__ o0, float* __restrict__ o1, int N)
{
    int t = blockIdx.x * blockDim.x + threadIdx.x;
    int n = t >> 5;
    if (n >= N) return;
    int lane = t & 31;

    int beg = __ldg(&ptr[n]);
    int end = beg + __ldg(&cnt[n]);
    float4 a0 = make_float4(0.f, 0.f, 0.f, 0.f);
    float4 a1 = a0;

    int e = beg;
    for (; e + 2 <= end; e += 2) {
        int sA = __ldg(&ci[e]), sB = __ldg(&ci[e+1]);
        float wA = __ldg(&wv[e]), wB = __ldg(&wv[e+1]);
        size_t oA = (size_t)sA * 64 + lane * 2;
        size_t oB = (size_t)sB * 64 + lane * 2;
        uint2 vA0 = *(const uint2*)&x0[oA];
        uint2 vB0 = *(const uint2*)&x0[oB];
        uint2 vA1 = *(const uint2*)&x1[oA];
        uint2 vB1 = *(const uint2*)&x1[oB];
        acc_bf2(a0, vA0, wA); acc_bf2(a0, vB0, wB);
        acc_bf2(a1, vA1, wA); acc_bf2(a1, vB1, wB);
    }
    for (; e < end; e++) {
        int s = __ldg(&ci[e]);
        float w0 = __ldg(&wv[e]);
        size_t o = (size_t)s * 64 + lane * 2;
        uint2 v0 = *(const uint2*)&x0[o];
        uint2 v1 = *(const uint2*)&x1[o];
        acc_bf2(a0, v0, w0);
        acc_bf2(a1, v1, w0);
    }
    size_t od = (size_t)n * 128 + lane * 4;
    *(float4*)&o0[od] = a0;
    *(float4*)&o1[od] = a1;
}

// x0,x1 bf16; x2 (word_emb) fp32
__global__ __launch_bounds__(256) void gather3_kernel(
    const int* __restrict__ ptr, const int* __restrict__ cnt,
    const int* __restrict__ ci, const float* __restrict__ wv,
    const u32* __restrict__ x0, const u32* __restrict__ x1,
    const float* __restrict__ x2,
    float* __restrict__ o0, float* __restrict__ o1, float* __restrict__ o2, int N)
{
    int t = blockIdx.x * blockDim.x + threadIdx.x;
    int n = t >> 5;
    if (n >= N) return;
    int lane = t & 31;

    int beg = __ldg(&ptr[n]);
    int end = beg + __ldg(&cnt[n]);
    float4 a0 = make_float4(0.f, 0.f, 0.f, 0.f);
    float4 a1 = a0, a2 = a0;

    int e = beg;
    for (; e + 2 <= end; e += 2) {
        int sA = __ldg(&ci[e]), sB = __ldg(&ci[e+1]);
        float wA = __ldg(&wv[e]), wB = __ldg(&wv[e+1]);
        size_t oA = (size_t)sA * 64 + lane * 2;
        size_t oB = (size_t)sB * 64 + lane * 2;
        uint2 vA0 = *(const uint2*)&x0[oA];
        uint2 vB0 = *(const uint2*)&x0[oB];
        uint2 vA1 = *(const uint2*)&x1[oA];
        uint2 vB1 = *(const uint2*)&x1[oB];
        float4 vA2 = *(const float4*)&x2[(size_t)sA * 128 + lane * 4];
        float4 vB2 = *(const float4*)&x2[(size_t)sB * 128 + lane * 4];
        acc_bf2(a0, vA0, wA); acc_bf2(a0, vB0, wB);
        acc_bf2(a1, vA1, wA); acc_bf2(a1, vB1, wB);
        a2.x = fmaf(wA, vA2.x, fmaf(wB, vB2.x, a2.x));
        a2.y = fmaf(wA, vA2.y, fmaf(wB, vB2.y, a2.y));
        a2.z = fmaf(wA, vA2.z, fmaf(wB, vB2.z, a2.z));
        a2.w = fmaf(wA, vA2.w, fmaf(wB, vB2.w, a2.w));
    }
    for (; e < end; e++) {
        int s = __ldg(&ci[e]);
        float w0 = __ldg(&wv[e]);
        size_t o = (size_t)s * 64 + lane * 2;
        uint2 v0 = *(const uint2*)&x0[o];
        uint2 v1 = *(const uint2*)&x1[o];
        float4 v2 = *(const float4*)&x2[(size_t)s * 128 + lane * 4];
        acc_bf2(a0, v0, w0);
        acc_bf2(a1, v1, w0);
        a2.x = fmaf(w0, v2.x, a2.x);
        a2.y = fmaf(w0, v2.y, a2.y);
        a2.z = fmaf(w0, v2.z, a2.z);
        a2.w = fmaf(w0, v2.w, a2.w);
    }
    size_t od = (size_t)n * 128 + lane * 4;
    *(float4*)&o0[od] = a0;
    *(float4*)&o1[od] = a1;
    *(float4*)&o2[od] = a2;
}

// ===========================================================================
// Final epilogue (unchanged)
// ===========================================================================
__global__ __launch_bounds__(128) void finalize_kernel(
    const float* __restrict__ r0, const float* __restrict__ rA,
    const float* __restrict__ rw, const float* __restrict__ r0s,
    const float* __restrict__ rB, float* __restrict__ out)
{
    const int n = blockIdx.x;
    const int t = threadIdx.x;
    const int lane = t & 31, wid = t >> 5;

    const size_t base = (size_t)n * 128 + t;
    float v0  = r0 [base];
    float vA  = rA [base];
    float vW  = rw [base];
    float v0s = r0s[base];
    float vB  = rB [base];

    float4 sq = make_float4(v0 * v0, vA * vA + vW * vW,
                            v0s * v0s, vB * vB + vW * vW);
#pragma unroll
    for (int o = 16; o; o >>= 1) {
        sq.x += __shfl_xor_sync(0xffffffffu, sq.x, o);
        sq.y += __shfl_xor_sync(0xffffffffu, sq.y, o);
        sq.z += __shfl_xor_sync(0xffffffffu, sq.z, o);
        sq.w += __shfl_xor_sync(0xffffffffu, sq.w, o);
    }
    __shared__ float4 wsum[4];
    if (lane == 0) wsum[wid] = sq;
    __syncthreads();
    float s0  = wsum[0].x + wsum[1].x + wsum[2].x + wsum[3].x;
    float s1  = wsum[0].y + wsum[1].y + wsum[2].y + wsum[3].y;
    float s0s = wsum[0].z + wsum[1].z + wsum[2].z + wsum[3].z;
    float s1s = wsum[0].w + wsum[1].w + wsum[2].w + wsum[3].w;

    const float EPS = 1e-9f;
    float i0  = 1.f / (sqrtf(s0)  + EPS);
    float i1  = 1.f / (sqrtf(s1)  + EPS);
    float i0s = 1.f / (sqrtf(s0s) + EPS);
    float i1s = 1.f / (sqrtf(s1s) + EPS);

    size_t drow = (size_t)n * 384;
    out[drow + t]       = v0 * i0;
    out[drow + 128 + t] = vA * i1;
    out[drow + 256 + t] = vW * i1;

    size_t srow = (size_t)N0_DOCS * 384 + drow;
    out[srow + t]       = v0s * i0s;
    out[srow + 128 + t] = vB * i1s;
    out[srow + 256 + t] = vW * i1s;
}

// ===========================================================================
// Launch
// ===========================================================================
extern "C" void kernel_launch(void* const* d_in, const int* in_sizes, int n_in,
                              void* d_out, int out_size)
{
    const float* x1       = (const float*)d_in[0];
    const float* x2       = (const float*)d_in[1];
    const float* word_emb = (const float*)d_in[2];
    const float* W1a = (const float*)d_in[3];
    const float* b1a = (const float*)d_in[4];
    const float* W1b = (const float*)d_in[5];
    const float* b1b = (const float*)d_in[6];
    const float* W2a = (const float*)d_in[7];
    const float* b2a = (const float*)d_in[8];
    const float* W2b = (const float*)d_in[9];
    const float* b2b = (const float*)d_in[10];
    const int*   e11_src = (const int*)d_in[11];
    const int*   e11_dst = (const int*)d_in[12];
    const float* e11_w   = (const float*)d_in[13];
    const int*   e22_src = (const int*)d_in[14];
    const int*   e22_dst = (const int*)d_in[15];
    const float* e22_w   = (const float*)d_in[16];
    const int*   e01_src = (const int*)d_in[17];
    const int*   e01_dst = (const int*)d_in[18];
    const float* e01_w   = (const float*)d_in[19];
    const int*   e02_src = (const int*)d_in[20];
    const int*   e02_dst = (const int*)d_in[21];
    const float* e02_w   = (const float*)d_in[22];

    const int N1  = in_sizes[0] / 256;
    const int N2  = in_sizes[1] / 256;
    const int E11 = in_sizes[11];
    const int E22 = in_sizes[14];
    const int E01 = in_sizes[17];
    const int E02 = in_sizes[20];
    const int Etot = E11 + E22 + E01 + E02;
    const int Ntot = N1 + N2 + 2 * N0_DOCS;
    const int b22 = N1, b01 = N1 + N2, b02 = N1 + N2 + N0_DOCS;

    u32 *l1_1, *l2_1, *l1_2, *l2_2;
    float *h1, *h2, *r0, *r0s, *rA, *rB, *rw;
    cudaGetSymbolAddress((void**)&l1_1, g_l1_1);
    cudaGetSymbolAddress((void**)&l2_1, g_l2_1);
    cudaGetSymbolAddress((void**)&l1_2, g_l1_2);
    cudaGetSymbolAddress((void**)&l2_2, g_l2_2);
    cudaGetSymbolAddress((void**)&h1,   g_h1);
    cudaGetSymbolAddress((void**)&h2,   g_h2);
    cudaGetSymbolAddress((void**)&r0,   g_r0);
    cudaGetSymbolAddress((void**)&r0s,  g_r0s);
    cudaGetSymbolAddress((void**)&rA,   g_rA);
    cudaGetSymbolAddress((void**)&rB,   g_rB);
    cudaGetSymbolAddress((void**)&rw,   g_rw);

    int *cntfc, *ptr, *ci, *bsum;
    float *wv;
    cudaGetSymbolAddress((void**)&cntfc, g_cntfc);
    cudaGetSymbolAddress((void**)&ptr,   g_ptr);
    cudaGetSymbolAddress((void**)&ci,    g_ci);
    cudaGetSymbolAddress((void**)&wv,    g_wv);
    cudaGetSymbolAddress((void**)&bsum,  g_bsum);
    int* cnt = cntfc;
    int* fc  = cntfc + NTOT;

    static cudaStream_t s1 = nullptr, s2 = nullptr, s3 = nullptr;
    static cudaEvent_t ev0 = nullptr, ev1 = nullptr, ev2 = nullptr, ecsr = nullptr;
    if (s1 == nullptr) {
        cudaStreamCreateWithFlags(&s1, cudaStreamNonBlocking);
        cudaStreamCreateWithFlags(&s2, cudaStreamNonBlocking);
        cudaStreamCreateWithFlags(&s3, cudaStreamNonBlocking);
        cudaEventCreateWithFlags(&ev0, cudaEventDisableTiming);
        cudaEventCreateWithFlags(&ev1, cudaEventDisableTiming);
        cudaEventCreateWithFlags(&ev2, cudaEventDisableTiming);
        cudaEventCreateWithFlags(&ecsr, cudaEventDisableTiming);
        cudaFuncSetAttribute(gemm_mma_kernel<1>,
                             cudaFuncAttributeMaxDynamicSharedMemorySize, GEMM_SMEM);
    }

    // Fork
    cudaEventRecord(ev0, 0);
    cudaStreamWaitEvent(s1, ev0, 0);
    cudaStreamWaitEvent(s2, ev0, 0);
    cudaStreamWaitEvent(s3, ev0, 0);

    // ---- stream 3: fused CSR build ----
    cudaMemsetAsync(cntfc, 0, 2 * NTOT * sizeof(int), s3);
    hist_all_kernel<<<(Etot + 255) / 256, 256, 0, s3>>>(
        e11_dst, e22_dst, e01_dst, e02_dst, E11, E22, E01, E02,
        b22, b01, b02, cnt);
    int nb = (Ntot + SCB - 1) / SCB;
    scan1_kernel<<<nb, SCB, 0, s3>>>(cnt, ptr, bsum, Ntot);
    scan2_kernel<<<1, SCB, 0, s3>>>(bsum, nb);
    scan3_kernel<<<nb, SCB, 0, s3>>>(ptr, bsum, Ntot);
    fill_all_kernel<<<(Etot + 255) / 256, 256, 0, s3>>>(
        e11_src, e11_dst, e11_w, e22_src, e22_dst, e22_w,
        e01_src, e01_dst, e01_w, e02_src, e02_dst, e02_w,
        E11, E22, E01, E02, b22, b01, b02, ptr, fc, ci, wv);
    cudaEventRecord(ecsr, s3);

    // ---- stream 1: type-1 pipeline ----
    gemm_mma_kernel<1><<<(N1 + 127) / 128, 256, GEMM_SMEM, s1>>>(
        x1, W1a, b1a, l1_1, N1, 256);
    cudaStreamWaitEvent(s1, ecsr, 0);
    gather1_kernel<<<(N1 * 32 + 255) / 256, 256, 0, s1>>>(
        ptr, cnt, ci, wv, l1_1, h1, N1);
    gemm_mma_kernel<1><<<(N1 + 127) / 128, 256, GEMM_SMEM, s1>>>(
        h1, W1b, b1b, l2_1, N1, 128);
    gather2_kernel<<<(N0_DOCS * 32 + 255) / 256, 256, 0, s1>>>(
        ptr + b01, cnt + b01, ci, wv, l2_1, l1_1, r0, r0s, N0_DOCS);
    cudaEventRecord(ev1, s1);

    // ---- stream 2: type-2 pipeline ----
    gemm_mma_kernel<1><<<(N2 + 127) / 128, 256, GEMM_SMEM, s2>>>(
        x2, W2a, b2a, l1_2, N2, 256);
    cudaStreamWaitEvent(s2, ecsr, 0);
    gather1_kernel<<<(N2 * 32 + 255) / 256, 256, 0, s2>>>(
        ptr + b22, cnt + b22, ci, wv, l1_2, h2, N2);
    gemm_mma_kernel<1><<<(N2 + 127) / 128, 256, GEMM_SMEM, s2>>>(
        h2, W2b, b2b, l2_2, N2, 128);
    gather3_kernel<<<(N0_DOCS * 32 + 255) / 256, 256, 0, s2>>>(
        ptr + b02, cnt + b02, ci, wv, l2_2, l1_2, word_emb, rA, rB, rw, N0_DOCS);
    cudaEventRecord(ev2, s2);

    // ---- join + finalize ----
    cudaStreamWaitEvent(0, ev1, 0);
    cudaStreamWaitEvent(0, ev2, 0);
    finalize_kernel<<<N0_DOCS, 128, 0, 0>>>(r0, rA, rw, r0s, rB, (float*)d_out);
}